// round 3
// baseline (speedup 1.0000x reference)
#include <cuda_runtime.h>
#include <math.h>

#define B_   4
#define S_   2048
#define H_   12
#define DM   768
#define DL   128
#define DQK  128
#define DV   128
#define MTOK (B_*S_)   // 8192

// ---------------- scratch (static device allocations; no runtime alloc) ------
__device__ float g_Ckv  [MTOK*DL];
__device__ float g_Cq   [MTOK*DL];
__device__ float g_qnope[MTOK*H_*64];
__device__ float g_qrope[MTOK*H_*64];
__device__ float g_knope[MTOK*H_*64];
__device__ float g_krope[MTOK*H_*64];
__device__ float g_v    [MTOK*H_*DV];                 // (b,s,h,dv)
__device__ float g_q    [B_*H_*S_*DQK];               // (b*h, s, d)
__device__ float g_k    [B_*H_*S_*DQK];
__device__ float g_o    [MTOK*H_*DV];                 // (b,s,h,dv)

// ---------------- generic GEMM: C[m,n] = sum_k A[m,k]*W[n,k] + bias[n] -------
// BM=BN=64, BK=16, 256 threads, 4x4 microtile. All shapes divide exactly.
__global__ void gemm_abt(const float* __restrict__ A, const float* __restrict__ W,
                         const float* __restrict__ bias, float* __restrict__ C,
                         int M, int N, int K) {
    __shared__ float As[64][17];
    __shared__ float Bs[64][17];
    const int tid = threadIdx.x;
    const int tx = tid & 15, ty = tid >> 4;
    const int m0 = blockIdx.y << 6, n0 = blockIdx.x << 6;
    const int lr = tid >> 2, lc = (tid & 3) << 2;
    float acc[4][4] = {};
    const float* Ag = A + (size_t)(m0 + lr) * K + lc;
    const float* Wg = W + (size_t)(n0 + lr) * K + lc;
    for (int k0 = 0; k0 < K; k0 += 16) {
        float4 av = *(const float4*)(Ag + k0);
        float4 wv = *(const float4*)(Wg + k0);
        __syncthreads();
        As[lr][lc+0] = av.x; As[lr][lc+1] = av.y; As[lr][lc+2] = av.z; As[lr][lc+3] = av.w;
        Bs[lr][lc+0] = wv.x; Bs[lr][lc+1] = wv.y; Bs[lr][lc+2] = wv.z; Bs[lr][lc+3] = wv.w;
        __syncthreads();
        #pragma unroll
        for (int kk = 0; kk < 16; ++kk) {
            float a[4], b[4];
            #pragma unroll
            for (int i = 0; i < 4; ++i) a[i] = As[(ty << 2) + i][kk];
            #pragma unroll
            for (int j = 0; j < 4; ++j) b[j] = Bs[(tx << 2) + j][kk];
            #pragma unroll
            for (int i = 0; i < 4; ++i)
                #pragma unroll
                for (int j = 0; j < 4; ++j)
                    acc[i][j] = fmaf(a[i], b[j], acc[i][j]);
        }
    }
    #pragma unroll
    for (int i = 0; i < 4; ++i) {
        int m = m0 + (ty << 2) + i;
        #pragma unroll
        for (int j = 0; j < 4; ++j) {
            int n = n0 + (tx << 2) + j;
            C[(size_t)m * N + n] = acc[i][j] + bias[n];
        }
    }
}

// ---------------- RoPE + head repack ----------------------------------------
// Reference: q = concat([q_nope(768), q_rope(768)]) -> 1536, reshape (H=12,128).
// Head h takes CONTIGUOUS concat dims [h*128,(h+1)*128). So heads 0-5 come
// entirely from the nope projection, heads 6-11 entirely from the rope
// projection. RoPE is applied over the FULL 768-dim rope vector before the
// concat: pair p = element e/2, inv_freq exponent = 2p/768.
// One thread per (token m, pair p in [0,384)).
__global__ void pack_qk(const int* __restrict__ pos) {
    int idx = blockIdx.x * blockDim.x + threadIdx.x;
    if (idx >= MTOK * 384) return;
    int p = idx % 384;
    int m = idx / 384;
    int s = m & (S_ - 1);
    int b = m >> 11;                                   // S_ = 2048

    size_t nb = (size_t)m * 768;

    // ---- nope pair: concat dim c = 2p (< 768) -> head c/128, dim c%128 ----
    {
        int c = 2 * p;
        int h = c >> 7, d = c & 127;
        size_t ob = ((size_t)(b * H_ + h) * S_ + s) * DQK + d;
        g_q[ob]     = g_qnope[nb + c];
        g_q[ob + 1] = g_qnope[nb + c + 1];
        g_k[ob]     = g_knope[nb + c];
        g_k[ob + 1] = g_knope[nb + c + 1];
    }

    // ---- rope pair: concat dim c = 768 + 2p -> head 6 + p/64 --------------
    {
        float inv_freq = powf(10000.0f, -(float)(2 * p) / 768.0f);
        float ang = (float)pos[s] * inv_freq;
        float sn, cs;
        sincosf(ang, &sn, &cs);
        int e = 2 * p;                 // element index within the 768 rope vec
        int h = 6 + (e >> 7), d = e & 127;
        size_t ob = ((size_t)(b * H_ + h) * S_ + s) * DQK + d;
        float qe = g_qrope[nb + e], qo = g_qrope[nb + e + 1];
        g_q[ob]     = qe * cs - qo * sn;
        g_q[ob + 1] = qe * sn + qo * cs;
        float ke = g_krope[nb + e], ko = g_krope[nb + e + 1];
        g_k[ob]     = ke * cs - ko * sn;
        g_k[ob + 1] = ke * sn + ko * cs;
    }
}

// ---------------- flash attention (fp32, online softmax) --------------------
// Block: 256 threads = 64 q-rows x 4 lanes. Each lane owns d-quarter kp*32..+32
// of its q row (registers) and output cols kp*32..+32.
// K/V smem rows use chunked layout: 4 chunks of 36 floats (row stride 144)
// so the 4 lanes' float4 reads land on distinct banks (broadcast across rows).
#define KCH  36
#define KROW 144
#define PROW 68
#define ATT_SMEM ((64*KROW*2 + 64*PROW) * 4)   // 91136 bytes

__global__ __launch_bounds__(256, 2) void attn_kernel() {
    extern __shared__ float sm[];
    float* Ks = sm;
    float* Vs = sm + 64 * KROW;
    float* Ps = Vs + 64 * KROW;
    const int qt  = blockIdx.x;       // q tile (0..31)
    const int bh  = blockIdx.y;       // 0..47
    const int b   = bh / H_, h = bh % H_;
    const int tid = threadIdx.x;
    const int row = tid >> 2;         // 0..63
    const int kp  = tid & 3;          // lane quarter
    const float scale = 0.0883883476483184f;   // 1/sqrt(128)
    const int qglob = qt * 64 + row;

    // q quarter -> registers
    float qreg[32];
    const float* qg = g_q + ((size_t)bh * S_ + qglob) * DQK + kp * 32;
    #pragma unroll
    for (int j4 = 0; j4 < 8; ++j4) {
        float4 v = *(const float4*)(qg + 4 * j4);
        qreg[4*j4] = v.x; qreg[4*j4+1] = v.y; qreg[4*j4+2] = v.z; qreg[4*j4+3] = v.w;
    }

    float m_i = -INFINITY, l_i = 0.f;
    float acc[32];
    #pragma unroll
    for (int j = 0; j < 32; ++j) acc[j] = 0.f;

    const float* kg = g_k + (size_t)bh * S_ * DQK;
    const float* vg = g_v + (size_t)b * S_ * (H_ * DV) + h * DV;

    for (int t = 0; t <= qt; ++t) {
        __syncthreads();                    // previous PV done before overwrite
        for (int i = tid; i < 64 * 32; i += 256) {
            int r = i >> 5, d4 = i & 31;
            int chunk = d4 >> 3, w = d4 & 7;
            float4 kv = *(const float4*)(kg + (size_t)(t*64 + r) * DQK + d4 * 4);
            *(float4*)(Ks + r * KROW + chunk * KCH + w * 4) = kv;
            float4 vv = *(const float4*)(vg + (size_t)(t*64 + r) * (H_*DV) + d4 * 4);
            *(float4*)(Vs + r * KROW + chunk * KCH + w * 4) = vv;
        }
        __syncthreads();

        float sv[16];
        float mloc = -INFINITY;
        const bool diag = (t == qt);
        #pragma unroll
        for (int kk = 0; kk < 16; ++kk) {
            #pragma unroll
            for (int kq = 0; kq < 4; ++kq) {
                int k = kk * 4 + kq;
                const float* kr = Ks + k * KROW + kp * KCH;
                float dot = 0.f;
                #pragma unroll
                for (int j4 = 0; j4 < 8; ++j4) {
                    float4 kv = *(const float4*)(kr + 4 * j4);
                    dot = fmaf(qreg[4*j4+0], kv.x, dot);
                    dot = fmaf(qreg[4*j4+1], kv.y, dot);
                    dot = fmaf(qreg[4*j4+2], kv.z, dot);
                    dot = fmaf(qreg[4*j4+3], kv.w, dot);
                }
                dot += __shfl_xor_sync(0xffffffffu, dot, 1);
                dot += __shfl_xor_sync(0xffffffffu, dot, 2);
                if (kq == kp) {                        // this lane keeps k = 4*kk+kp
                    dot *= scale;
                    if (diag && (t * 64 + k) > qglob) dot = -INFINITY;
                    sv[kk] = dot;
                    mloc = fmaxf(mloc, dot);
                }
            }
        }
        mloc = fmaxf(mloc, __shfl_xor_sync(0xffffffffu, mloc, 1));
        mloc = fmaxf(mloc, __shfl_xor_sync(0xffffffffu, mloc, 2));
        float m_new = fmaxf(m_i, mloc);
        float alpha = expf(m_i - m_new);               // expf(-inf)=0 first tile
        float lsum = 0.f;
        #pragma unroll
        for (int kk = 0; kk < 16; ++kk) {
            float p = expf(sv[kk] - m_new);
            Ps[row * PROW + kk * 4 + kp] = p;
            lsum += p;
        }
        lsum += __shfl_xor_sync(0xffffffffu, lsum, 1);
        lsum += __shfl_xor_sync(0xffffffffu, lsum, 2);
        l_i = l_i * alpha + lsum;
        m_i = m_new;
        #pragma unroll
        for (int j = 0; j < 32; ++j) acc[j] *= alpha;
        __syncwarp();                                  // Ps row is warp-private
        #pragma unroll 4
        for (int k = 0; k < 64; ++k) {
            float p = Ps[row * PROW + k];
            const float* vr = Vs + k * KROW + kp * KCH;
            #pragma unroll
            for (int j4 = 0; j4 < 8; ++j4) {
                float4 vv = *(const float4*)(vr + 4 * j4);
                acc[4*j4+0] = fmaf(p, vv.x, acc[4*j4+0]);
                acc[4*j4+1] = fmaf(p, vv.y, acc[4*j4+1]);
                acc[4*j4+2] = fmaf(p, vv.z, acc[4*j4+2]);
                acc[4*j4+3] = fmaf(p, vv.w, acc[4*j4+3]);
            }
        }
        __syncwarp();
    }
    float inv_l = 1.0f / l_i;
    float* og = g_o + ((size_t)(b * S_) + qglob) * (H_ * DV) + h * DV + kp * 32;
    #pragma unroll
    for (int j4 = 0; j4 < 8; ++j4) {
        float4 o4 = make_float4(acc[4*j4+0] * inv_l, acc[4*j4+1] * inv_l,
                                acc[4*j4+2] * inv_l, acc[4*j4+3] * inv_l);
        *(float4*)(og + 4 * j4) = o4;
    }
}

// ---------------- launcher ---------------------------------------------------
extern "C" void kernel_launch(void* const* d_in, const int* in_sizes, int n_in,
                              void* d_out, int out_size) {
    const float* x         = (const float*)d_in[0];
    const int*   pos       = (const int*)  d_in[1];
    const float* W_dkv     = (const float*)d_in[2];
    const float* b_dkv     = (const float*)d_in[3];
    const float* W_dq      = (const float*)d_in[4];
    const float* b_dq      = (const float*)d_in[5];
    const float* W_uk_nope = (const float*)d_in[6];
    const float* b_uk_nope = (const float*)d_in[7];
    const float* W_uv      = (const float*)d_in[8];
    const float* b_uv      = (const float*)d_in[9];
    const float* W_uq_nope = (const float*)d_in[10];
    const float* b_uq_nope = (const float*)d_in[11];
    const float* W_uq_rope = (const float*)d_in[12];
    const float* b_uq_rope = (const float*)d_in[13];
    const float* W_uk_rope = (const float*)d_in[14];
    const float* b_uk_rope = (const float*)d_in[15];
    const float* W_o       = (const float*)d_in[16];
    const float* b_o       = (const float*)d_in[17];
    float* out = (float*)d_out;

    float *Ckv, *Cq, *qn, *qr, *kn, *kr, *v, *o;
    cudaGetSymbolAddress((void**)&Ckv, g_Ckv);
    cudaGetSymbolAddress((void**)&Cq,  g_Cq);
    cudaGetSymbolAddress((void**)&qn,  g_qnope);
    cudaGetSymbolAddress((void**)&qr,  g_qrope);
    cudaGetSymbolAddress((void**)&kn,  g_knope);
    cudaGetSymbolAddress((void**)&kr,  g_krope);
    cudaGetSymbolAddress((void**)&v,   g_v);
    cudaGetSymbolAddress((void**)&o,   g_o);

    auto gemm = [&](const float* A, const float* W, const float* bias, float* C,
                    int M, int N, int K) {
        dim3 grid(N / 64, M / 64);
        gemm_abt<<<grid, 256>>>(A, W, bias, C, M, N, K);
    };

    gemm(x,   W_dkv,     b_dkv,     Ckv, MTOK, DL,      DM);
    gemm(x,   W_dq,      b_dq,      Cq,  MTOK, DL,      DM);
    gemm(Cq,  W_uq_nope, b_uq_nope, qn,  MTOK, H_*64,   DL);
    gemm(Cq,  W_uq_rope, b_uq_rope, qr,  MTOK, H_*64,   DL);
    gemm(Ckv, W_uk_nope, b_uk_nope, kn,  MTOK, H_*64,   DL);
    gemm(x,   W_uk_rope, b_uk_rope, kr,  MTOK, H_*64,   DM);
    gemm(Ckv, W_uv,      b_uv,      v,   MTOK, H_*DV,   DL);

    int packTotal = MTOK * 384;
    pack_qk<<<(packTotal + 255) / 256, 256>>>(pos);

    cudaFuncSetAttribute(attn_kernel, cudaFuncAttributeMaxDynamicSharedMemorySize,
                         ATT_SMEM);
    attn_kernel<<<dim3(S_ / 64, B_ * H_), 256, ATT_SMEM>>>();

    gemm(o, W_o, b_o, out, MTOK, DM, H_ * DV);
}

// round 5
// speedup vs baseline: 3.6689x; 3.6689x over previous
#include <cuda_runtime.h>
#include <math.h>

#define B_   4
#define S_   2048
#define H_   12
#define DM   768
#define DL   128
#define DQK  128
#define DV   128
#define MTOK (B_*S_)   // 8192

// ---------------- scratch ----------------------------------------------------
__device__ float g_Ckv  [MTOK*DL];
__device__ float g_Cq   [MTOK*DL];
__device__ float g_qnope[MTOK*H_*64];
__device__ float g_qrope[MTOK*H_*64];
__device__ float g_knope[MTOK*H_*64];
__device__ float g_krope[MTOK*H_*64];
__device__ float g_v    [MTOK*H_*DV];                 // (b,s,h,dv)
__device__ float g_q    [B_*H_*S_*DQK];               // (b*h, s, d)
__device__ float g_k    [B_*H_*S_*DQK];
__device__ float g_o    [MTOK*H_*DV];                 // (b,s,h,dv)

// ---------------- tf32 helpers ----------------------------------------------
__device__ __forceinline__ unsigned f2tf(float x) {
    unsigned r; asm("cvt.rna.tf32.f32 %0, %1;" : "=r"(r) : "f"(x)); return r;
}
__device__ __forceinline__ void mma8(float* d, const unsigned* a,
                                     const unsigned* b) {
    asm volatile(
        "mma.sync.aligned.m16n8k8.row.col.f32.tf32.tf32.f32 "
        "{%0,%1,%2,%3}, {%4,%5,%6,%7}, {%8,%9}, {%0,%1,%2,%3};"
        : "+f"(d[0]), "+f"(d[1]), "+f"(d[2]), "+f"(d[3])
        : "r"(a[0]), "r"(a[1]), "r"(a[2]), "r"(a[3]), "r"(b[0]), "r"(b[1]));
}

// ---------------- tf32 GEMM: C[m,n] = sum_k A[m,k]*W[n,k] + bias[n] ----------
// BM=BN=128, BK=16, 256 threads = 8 warps (2 along m x 4 along n), warp 64x32.
#define GSTR 20
__global__ __launch_bounds__(256) void gemm_tf32(
        const float* __restrict__ A, const float* __restrict__ W,
        const float* __restrict__ bias, float* __restrict__ C,
        int M, int N, int K) {
    __shared__ float As[128 * GSTR];
    __shared__ float Ws[128 * GSTR];
    const int tid = threadIdx.x, lane = tid & 31, wid = tid >> 5;
    const int m0 = blockIdx.y << 7, n0 = blockIdx.x << 7;
    const int wm = wid & 1, wn = wid >> 1;
    const int g  = lane >> 2, t4 = lane & 3;
    float acc[4][4][4];
    #pragma unroll
    for (int i = 0; i < 4; ++i)
        #pragma unroll
        for (int j = 0; j < 4; ++j)
            #pragma unroll
            for (int e = 0; e < 4; ++e) acc[i][j][e] = 0.f;

    const int lrow0 = tid >> 2, lcol = (tid & 3) << 2;
    float4 ar[2], wr_[2];
    {
        ar[0]  = *(const float4*)(A + (size_t)(m0 + lrow0) * K + lcol);
        ar[1]  = *(const float4*)(A + (size_t)(m0 + lrow0 + 64) * K + lcol);
        wr_[0] = *(const float4*)(W + (size_t)(n0 + lrow0) * K + lcol);
        wr_[1] = *(const float4*)(W + (size_t)(n0 + lrow0 + 64) * K + lcol);
    }
    for (int k0 = 0; k0 < K; k0 += 16) {
        __syncthreads();
        #pragma unroll
        for (int j = 0; j < 2; ++j) {
            int row = lrow0 + j * 64;
            float* pa = As + row * GSTR + lcol;
            pa[0] = __uint_as_float(f2tf(ar[j].x));
            pa[1] = __uint_as_float(f2tf(ar[j].y));
            pa[2] = __uint_as_float(f2tf(ar[j].z));
            pa[3] = __uint_as_float(f2tf(ar[j].w));
            float* pw = Ws + row * GSTR + lcol;
            pw[0] = __uint_as_float(f2tf(wr_[j].x));
            pw[1] = __uint_as_float(f2tf(wr_[j].y));
            pw[2] = __uint_as_float(f2tf(wr_[j].z));
            pw[3] = __uint_as_float(f2tf(wr_[j].w));
        }
        __syncthreads();
        if (k0 + 16 < K) {
            int kc = k0 + 16 + lcol;
            ar[0]  = *(const float4*)(A + (size_t)(m0 + lrow0) * K + kc);
            ar[1]  = *(const float4*)(A + (size_t)(m0 + lrow0 + 64) * K + kc);
            wr_[0] = *(const float4*)(W + (size_t)(n0 + lrow0) * K + kc);
            wr_[1] = *(const float4*)(W + (size_t)(n0 + lrow0 + 64) * K + kc);
        }
        #pragma unroll
        for (int ks = 0; ks < 2; ++ks) {
            unsigned af[4][4], bf[4][2];
            #pragma unroll
            for (int mf = 0; mf < 4; ++mf) {
                int row = wm * 64 + mf * 16 + g;
                int col = ks * 8 + t4;
                af[mf][0] = __float_as_uint(As[row * GSTR + col]);
                af[mf][1] = __float_as_uint(As[(row + 8) * GSTR + col]);
                af[mf][2] = __float_as_uint(As[row * GSTR + col + 4]);
                af[mf][3] = __float_as_uint(As[(row + 8) * GSTR + col + 4]);
            }
            #pragma unroll
            for (int nf = 0; nf < 4; ++nf) {
                int n = wn * 32 + nf * 8 + g;
                int kk = ks * 8 + t4;
                bf[nf][0] = __float_as_uint(Ws[n * GSTR + kk]);
                bf[nf][1] = __float_as_uint(Ws[n * GSTR + kk + 4]);
            }
            #pragma unroll
            for (int mf = 0; mf < 4; ++mf)
                #pragma unroll
                for (int nf = 0; nf < 4; ++nf)
                    mma8(acc[mf][nf], af[mf], bf[nf]);
        }
    }
    #pragma unroll
    for (int mf = 0; mf < 4; ++mf) {
        int row = m0 + wm * 64 + mf * 16 + g;
        #pragma unroll
        for (int nf = 0; nf < 4; ++nf) {
            int col = n0 + wn * 32 + nf * 8 + 2 * t4;
            float b0 = bias[col], b1 = bias[col + 1];
            C[(size_t)row * N + col]           = acc[mf][nf][0] + b0;
            C[(size_t)row * N + col + 1]       = acc[mf][nf][1] + b1;
            C[(size_t)(row + 8) * N + col]     = acc[mf][nf][2] + b0;
            C[(size_t)(row + 8) * N + col + 1] = acc[mf][nf][3] + b1;
        }
    }
}

// ---------------- RoPE + head repack (validated in R3) -----------------------
__global__ void pack_qk(const int* __restrict__ pos) {
    int idx = blockIdx.x * blockDim.x + threadIdx.x;
    if (idx >= MTOK * 384) return;
    int p = idx % 384;
    int m = idx / 384;
    int s = m & (S_ - 1);
    int b = m >> 11;
    size_t nb = (size_t)m * 768;
    {   // nope pair -> heads 0-5
        int c = 2 * p;
        int h = c >> 7, d = c & 127;
        size_t ob = ((size_t)(b * H_ + h) * S_ + s) * DQK + d;
        g_q[ob]     = g_qnope[nb + c];
        g_q[ob + 1] = g_qnope[nb + c + 1];
        g_k[ob]     = g_knope[nb + c];
        g_k[ob + 1] = g_knope[nb + c + 1];
    }
    {   // rope pair -> heads 6-11, freq over full 768-dim vector
        float inv_freq = powf(10000.0f, -(float)(2 * p) / 768.0f);
        float ang = (float)pos[s] * inv_freq;
        float sn, cs;
        sincosf(ang, &sn, &cs);
        int e = 2 * p;
        int h = 6 + (e >> 7), d = e & 127;
        size_t ob = ((size_t)(b * H_ + h) * S_ + s) * DQK + d;
        float qe = g_qrope[nb + e], qo = g_qrope[nb + e + 1];
        g_q[ob]     = qe * cs - qo * sn;
        g_q[ob + 1] = qe * sn + qo * cs;
        float ke = g_krope[nb + e], ko = g_krope[nb + e + 1];
        g_k[ob]     = ke * cs - ko * sn;
        g_k[ob + 1] = ke * sn + ko * cs;
    }
}

// ---------------- flash attention with tf32 mma ------------------------------
// CTA: 64 q-rows, 8 warps = 4 (q-row groups of 16) x 2 (wc).
// QK: warp computes 16 rows x 32 keys (wc splits the 64 keys).
// PV: warp computes 16 rows x 64 d-cols (wc splits DV=128).  <-- R4 fix
#define KSTR 132
#define PSTR 68
#define ATT_SMEM ((64*KSTR*2 + 64*PSTR + 128) * 4)

__global__ __launch_bounds__(256, 1) void attn_mma() {
    extern __shared__ float sm[];
    float* Ks = sm;
    float* Vs = Ks + 64 * KSTR;
    float* Ps = Vs + 64 * KSTR;
    float* Al = Ps + 64 * PSTR;
    float* Li = Al + 64;
    const int qt = blockIdx.x, bh = blockIdx.y;
    const int b = bh / H_, h = bh % H_;
    const int tid = threadIdx.x, lane = tid & 31, wid = tid >> 5;
    const int wr = wid >> 1, wc = wid & 1;
    const int g = lane >> 2, t4 = lane & 3;
    const float scale = 0.0883883476483184f;   // 1/sqrt(128)

    // preload Q a-frags (rows wr*16 .. wr*16+15 of this q tile)
    unsigned qa[16][4];
    const float* qb = g_q + ((size_t)bh * S_ + qt * 64 + wr * 16) * DQK;
    #pragma unroll
    for (int ks = 0; ks < 16; ++ks) {
        qa[ks][0] = f2tf(qb[(size_t)g * DQK + ks * 8 + t4]);
        qa[ks][1] = f2tf(qb[(size_t)(g + 8) * DQK + ks * 8 + t4]);
        qa[ks][2] = f2tf(qb[(size_t)g * DQK + ks * 8 + t4 + 4]);
        qa[ks][3] = f2tf(qb[(size_t)(g + 8) * DQK + ks * 8 + t4 + 4]);
    }

    float oc[8][4];
    #pragma unroll
    for (int i = 0; i < 8; ++i)
        #pragma unroll
        for (int j = 0; j < 4; ++j) oc[i][j] = 0.f;

    const int rs = tid >> 2, ln = tid & 3;   // softmax row ownership
    float m_i = -INFINITY, l_i = 0.f;

    const float* kg = g_k + (size_t)bh * S_ * DQK;
    const float* vg = g_v + (size_t)b * S_ * (H_ * DV) + h * DV;

    for (int t = 0; t <= qt; ++t) {
        __syncthreads();
        for (int i = tid; i < 2048; i += 256) {
            int rr = i >> 5, d4 = (i & 31) << 2;
            float4 kv = *(const float4*)(kg + (size_t)(t * 64 + rr) * DQK + d4);
            float* pk = Ks + rr * KSTR + d4;
            pk[0] = __uint_as_float(f2tf(kv.x));
            pk[1] = __uint_as_float(f2tf(kv.y));
            pk[2] = __uint_as_float(f2tf(kv.z));
            pk[3] = __uint_as_float(f2tf(kv.w));
            float4 vv = *(const float4*)(vg + (size_t)(t * 64 + rr) * (H_*DV) + d4);
            float* pv = Vs + rr * KSTR + d4;
            pv[0] = __uint_as_float(f2tf(vv.x));
            pv[1] = __uint_as_float(f2tf(vv.y));
            pv[2] = __uint_as_float(f2tf(vv.z));
            pv[3] = __uint_as_float(f2tf(vv.w));
        }
        __syncthreads();

        // S = Q K^T  (warp: 16 q-rows x 32 keys)
        float sc[4][4];
        #pragma unroll
        for (int i = 0; i < 4; ++i)
            #pragma unroll
            for (int j = 0; j < 4; ++j) sc[i][j] = 0.f;
        #pragma unroll
        for (int ks = 0; ks < 16; ++ks) {
            #pragma unroll
            for (int nf = 0; nf < 4; ++nf) {
                unsigned kb[2];
                int key = wc * 32 + nf * 8 + g;
                kb[0] = __float_as_uint(Ks[key * KSTR + ks * 8 + t4]);
                kb[1] = __float_as_uint(Ks[key * KSTR + ks * 8 + t4 + 4]);
                mma8(sc[nf], qa[ks], kb);
            }
        }
        const bool diag = (t == qt);
        #pragma unroll
        for (int nf = 0; nf < 4; ++nf) {
            int kl = wc * 32 + nf * 8 + 2 * t4;
            int rl = wr * 16 + g;
            int kgl = t * 64 + kl;
            int rgl = qt * 64 + rl;
            float v0 = sc[nf][0] * scale, v1 = sc[nf][1] * scale;
            float v2 = sc[nf][2] * scale, v3 = sc[nf][3] * scale;
            if (diag) {
                if (kgl     > rgl)     v0 = -1e30f;
                if (kgl + 1 > rgl)     v1 = -1e30f;
                if (kgl     > rgl + 8) v2 = -1e30f;
                if (kgl + 1 > rgl + 8) v3 = -1e30f;
            }
            Ps[rl * PSTR + kl]           = v0;
            Ps[rl * PSTR + kl + 1]       = v1;
            Ps[(rl + 8) * PSTR + kl]     = v2;
            Ps[(rl + 8) * PSTR + kl + 1] = v3;
        }
        __syncthreads();

        // online softmax: 64 rows x 4 lanes, 16 cols each
        float pv[16];
        float mloc = -1e30f;
        #pragma unroll
        for (int j4 = 0; j4 < 4; ++j4) {
            float4 v = *(const float4*)(Ps + rs * PSTR + ln * 16 + 4 * j4);
            pv[4*j4] = v.x; pv[4*j4+1] = v.y; pv[4*j4+2] = v.z; pv[4*j4+3] = v.w;
            mloc = fmaxf(mloc, fmaxf(fmaxf(v.x, v.y), fmaxf(v.z, v.w)));
        }
        mloc = fmaxf(mloc, __shfl_xor_sync(0xffffffffu, mloc, 1));
        mloc = fmaxf(mloc, __shfl_xor_sync(0xffffffffu, mloc, 2));
        float m_new = fmaxf(m_i, mloc);
        float alpha = __expf(m_i - m_new);
        float lsum = 0.f;
        #pragma unroll
        for (int j4 = 0; j4 < 4; ++j4) {
            float4 o4;
            float p0 = __expf(pv[4*j4]   - m_new);
            float p1 = __expf(pv[4*j4+1] - m_new);
            float p2 = __expf(pv[4*j4+2] - m_new);
            float p3 = __expf(pv[4*j4+3] - m_new);
            lsum += (p0 + p1) + (p2 + p3);
            o4.x = __uint_as_float(f2tf(p0));
            o4.y = __uint_as_float(f2tf(p1));
            o4.z = __uint_as_float(f2tf(p2));
            o4.w = __uint_as_float(f2tf(p3));
            *(float4*)(Ps + rs * PSTR + ln * 16 + 4 * j4) = o4;
        }
        lsum += __shfl_xor_sync(0xffffffffu, lsum, 1);
        lsum += __shfl_xor_sync(0xffffffffu, lsum, 2);
        l_i = l_i * alpha + lsum;
        m_i = m_new;
        if (ln == 0) Al[rs] = alpha;
        __syncthreads();

        // rescale all 8 d-blocks
        float a0 = Al[wr * 16 + g], a1 = Al[wr * 16 + g + 8];
        #pragma unroll
        for (int nf = 0; nf < 8; ++nf) {
            oc[nf][0] *= a0; oc[nf][1] *= a0;
            oc[nf][2] *= a1; oc[nf][3] *= a1;
        }
        // O += P V  (warp: 16 q-rows x 64 d-cols; wc splits DV=128)
        #pragma unroll
        for (int ks = 0; ks < 8; ++ks) {
            unsigned pa[4];
            int rl = wr * 16 + g;
            pa[0] = __float_as_uint(Ps[rl * PSTR + ks * 8 + t4]);
            pa[1] = __float_as_uint(Ps[(rl + 8) * PSTR + ks * 8 + t4]);
            pa[2] = __float_as_uint(Ps[rl * PSTR + ks * 8 + t4 + 4]);
            pa[3] = __float_as_uint(Ps[(rl + 8) * PSTR + ks * 8 + t4 + 4]);
            #pragma unroll
            for (int nf = 0; nf < 8; ++nf) {
                unsigned vb[2];
                int dcol = wc * 64 + nf * 8 + g;
                vb[0] = __float_as_uint(Vs[(ks * 8 + t4) * KSTR + dcol]);
                vb[1] = __float_as_uint(Vs[(ks * 8 + t4 + 4) * KSTR + dcol]);
                mma8(oc[nf], pa, vb);
            }
        }
    }
    if (ln == 0) Li[rs] = 1.0f / l_i;
    __syncthreads();
    float li0 = Li[wr * 16 + g], li1 = Li[wr * 16 + g + 8];
    int rg = qt * 64 + wr * 16 + g;
    #pragma unroll
    for (int nf = 0; nf < 8; ++nf) {
        int dcol = wc * 64 + nf * 8 + 2 * t4;
        float* o0 = g_o + ((size_t)(b * S_) + rg) * (H_ * DV) + h * DV + dcol;
        float* o1 = o0 + 8 * (size_t)(H_ * DV);
        o0[0] = oc[nf][0] * li0; o0[1] = oc[nf][1] * li0;
        o1[0] = oc[nf][2] * li1; o1[1] = oc[nf][3] * li1;
    }
}

// ---------------- launcher ---------------------------------------------------
extern "C" void kernel_launch(void* const* d_in, const int* in_sizes, int n_in,
                              void* d_out, int out_size) {
    const float* x         = (const float*)d_in[0];
    const int*   pos       = (const int*)  d_in[1];
    const float* W_dkv     = (const float*)d_in[2];
    const float* b_dkv     = (const float*)d_in[3];
    const float* W_dq      = (const float*)d_in[4];
    const float* b_dq      = (const float*)d_in[5];
    const float* W_uk_nope = (const float*)d_in[6];
    const float* b_uk_nope = (const float*)d_in[7];
    const float* W_uv      = (const float*)d_in[8];
    const float* b_uv      = (const float*)d_in[9];
    const float* W_uq_nope = (const float*)d_in[10];
    const float* b_uq_nope = (const float*)d_in[11];
    const float* W_uq_rope = (const float*)d_in[12];
    const float* b_uq_rope = (const float*)d_in[13];
    const float* W_uk_rope = (const float*)d_in[14];
    const float* b_uk_rope = (const float*)d_in[15];
    const float* W_o       = (const float*)d_in[16];
    const float* b_o       = (const float*)d_in[17];
    float* out = (float*)d_out;

    float *Ckv, *Cq, *qn, *qr, *kn, *kr, *v, *o;
    cudaGetSymbolAddress((void**)&Ckv, g_Ckv);
    cudaGetSymbolAddress((void**)&Cq,  g_Cq);
    cudaGetSymbolAddress((void**)&qn,  g_qnope);
    cudaGetSymbolAddress((void**)&qr,  g_qrope);
    cudaGetSymbolAddress((void**)&kn,  g_knope);
    cudaGetSymbolAddress((void**)&kr,  g_krope);
    cudaGetSymbolAddress((void**)&v,   g_v);
    cudaGetSymbolAddress((void**)&o,   g_o);

    auto gemm = [&](const float* A, const float* W, const float* bias, float* C,
                    int M, int N, int K) {
        dim3 grid(N / 128, M / 128);
        gemm_tf32<<<grid, 256>>>(A, W, bias, C, M, N, K);
    };

    gemm(x,   W_dkv,     b_dkv,     Ckv, MTOK, DL,      DM);
    gemm(x,   W_dq,      b_dq,      Cq,  MTOK, DL,      DM);
    gemm(Cq,  W_uq_nope, b_uq_nope, qn,  MTOK, H_*64,   DL);
    gemm(Cq,  W_uq_rope, b_uq_rope, qr,  MTOK, H_*64,   DL);
    gemm(Ckv, W_uk_nope, b_uk_nope, kn,  MTOK, H_*64,   DL);
    gemm(x,   W_uk_rope, b_uk_rope, kr,  MTOK, H_*64,   DM);
    gemm(Ckv, W_uv,      b_uv,      v,   MTOK, H_*DV,   DL);

    int packTotal = MTOK * 384;
    pack_qk<<<(packTotal + 255) / 256, 256>>>(pos);

    cudaFuncSetAttribute(attn_mma, cudaFuncAttributeMaxDynamicSharedMemorySize,
                         ATT_SMEM);
    attn_mma<<<dim3(S_ / 64, B_ * H_), 256, ATT_SMEM>>>();

    gemm(o, W_o, b_o, out, MTOK, DM, H_ * DV);
}

// round 7
// speedup vs baseline: 3.7917x; 1.0335x over previous
#include <cuda_runtime.h>
#include <math.h>

#define B_   4
#define S_   2048
#define H_   12
#define DM   768
#define DL   128
#define DQK  128
#define DV   128
#define MTOK (B_*S_)   // 8192

// ---------------- scratch ----------------------------------------------------
__device__ float g_Ckv  [MTOK*DL];
__device__ float g_Cq   [MTOK*DL];
__device__ float g_qnope[MTOK*H_*64];
__device__ float g_qrope[MTOK*H_*64];
__device__ float g_knope[MTOK*H_*64];
__device__ float g_krope[MTOK*H_*64];
__device__ float g_v    [MTOK*H_*DV];                 // (b,s,h,dv)
__device__ float g_q    [B_*H_*S_*DQK];               // (b*h, s, d)
__device__ float g_k    [B_*H_*S_*DQK];
__device__ float g_o    [MTOK*H_*DV];                 // (b,s,h,dv)

// ---------------- tf32 helpers ----------------------------------------------
__device__ __forceinline__ unsigned f2tf(float x) {
    unsigned r; asm("cvt.rna.tf32.f32 %0, %1;" : "=r"(r) : "f"(x)); return r;
}
__device__ __forceinline__ void mma8(float* d, const unsigned* a,
                                     const unsigned* b) {
    asm volatile(
        "mma.sync.aligned.m16n8k8.row.col.f32.tf32.tf32.f32 "
        "{%0,%1,%2,%3}, {%4,%5,%6,%7}, {%8,%9}, {%0,%1,%2,%3};"
        : "+f"(d[0]), "+f"(d[1]), "+f"(d[2]), "+f"(d[3])
        : "r"(a[0]), "r"(a[1]), "r"(a[2]), "r"(a[3]), "r"(b[0]), "r"(b[1]));
}

// ---------------- tf32 GEMM (dual-job): C = A W^T + bias ---------------------
// blockIdx.z selects job. BM=BN=128, BK=16, 256 thr = 8 warps (2m x 4n).
struct GemmJob {
    const float* A; const float* W; const float* bias; float* C;
    int N; int K;
};

#define GSTR 20
__global__ __launch_bounds__(256) void gemm_tf32_dual(GemmJob j0, GemmJob j1) {
    const GemmJob j = blockIdx.z ? j1 : j0;
    const int N = j.N, K = j.K;
    const int n0 = blockIdx.x << 7;
    if (n0 >= N) return;
    const float* __restrict__ A = j.A;
    const float* __restrict__ W = j.W;
    __shared__ float As[128 * GSTR];
    __shared__ float Ws[128 * GSTR];
    const int tid = threadIdx.x, lane = tid & 31, wid = tid >> 5;
    const int m0 = blockIdx.y << 7;
    const int wm = wid & 1, wn = wid >> 1;
    const int g  = lane >> 2, t4 = lane & 3;
    float acc[4][4][4];
    #pragma unroll
    for (int i = 0; i < 4; ++i)
        #pragma unroll
        for (int jj = 0; jj < 4; ++jj)
            #pragma unroll
            for (int e = 0; e < 4; ++e) acc[i][jj][e] = 0.f;

    const int lrow0 = tid >> 2, lcol = (tid & 3) << 2;
    float4 ar[2], wr_[2];
    {
        ar[0]  = *(const float4*)(A + (size_t)(m0 + lrow0) * K + lcol);
        ar[1]  = *(const float4*)(A + (size_t)(m0 + lrow0 + 64) * K + lcol);
        wr_[0] = *(const float4*)(W + (size_t)(n0 + lrow0) * K + lcol);
        wr_[1] = *(const float4*)(W + (size_t)(n0 + lrow0 + 64) * K + lcol);
    }
    for (int k0 = 0; k0 < K; k0 += 16) {
        __syncthreads();
        #pragma unroll
        for (int jj = 0; jj < 2; ++jj) {
            int row = lrow0 + jj * 64;
            float* pa = As + row * GSTR + lcol;
            pa[0] = __uint_as_float(f2tf(ar[jj].x));
            pa[1] = __uint_as_float(f2tf(ar[jj].y));
            pa[2] = __uint_as_float(f2tf(ar[jj].z));
            pa[3] = __uint_as_float(f2tf(ar[jj].w));
            float* pw = Ws + row * GSTR + lcol;
            pw[0] = __uint_as_float(f2tf(wr_[jj].x));
            pw[1] = __uint_as_float(f2tf(wr_[jj].y));
            pw[2] = __uint_as_float(f2tf(wr_[jj].z));
            pw[3] = __uint_as_float(f2tf(wr_[jj].w));
        }
        __syncthreads();
        if (k0 + 16 < K) {
            int kc = k0 + 16 + lcol;
            ar[0]  = *(const float4*)(A + (size_t)(m0 + lrow0) * K + kc);
            ar[1]  = *(const float4*)(A + (size_t)(m0 + lrow0 + 64) * K + kc);
            wr_[0] = *(const float4*)(W + (size_t)(n0 + lrow0) * K + kc);
            wr_[1] = *(const float4*)(W + (size_t)(n0 + lrow0 + 64) * K + kc);
        }
        #pragma unroll
        for (int ks = 0; ks < 2; ++ks) {
            unsigned af[4][4], bf[4][2];
            #pragma unroll
            for (int mf = 0; mf < 4; ++mf) {
                int row = wm * 64 + mf * 16 + g;
                int col = ks * 8 + t4;
                af[mf][0] = __float_as_uint(As[row * GSTR + col]);
                af[mf][1] = __float_as_uint(As[(row + 8) * GSTR + col]);
                af[mf][2] = __float_as_uint(As[row * GSTR + col + 4]);
                af[mf][3] = __float_as_uint(As[(row + 8) * GSTR + col + 4]);
            }
            #pragma unroll
            for (int nf = 0; nf < 4; ++nf) {
                int n = wn * 32 + nf * 8 + g;
                int kk = ks * 8 + t4;
                bf[nf][0] = __float_as_uint(Ws[n * GSTR + kk]);
                bf[nf][1] = __float_as_uint(Ws[n * GSTR + kk + 4]);
            }
            #pragma unroll
            for (int mf = 0; mf < 4; ++mf)
                #pragma unroll
                for (int nf = 0; nf < 4; ++nf)
                    mma8(acc[mf][nf], af[mf], bf[nf]);
        }
    }
    #pragma unroll
    for (int mf = 0; mf < 4; ++mf) {
        int row = m0 + wm * 64 + mf * 16 + g;
        #pragma unroll
        for (int nf = 0; nf < 4; ++nf) {
            int col = n0 + wn * 32 + nf * 8 + 2 * t4;
            float b0 = j.bias[col], b1 = j.bias[col + 1];
            j.C[(size_t)row * N + col]           = acc[mf][nf][0] + b0;
            j.C[(size_t)row * N + col + 1]       = acc[mf][nf][1] + b1;
            j.C[(size_t)(row + 8) * N + col]     = acc[mf][nf][2] + b0;
            j.C[(size_t)(row + 8) * N + col + 1] = acc[mf][nf][3] + b1;
        }
    }
}

// ---------------- RoPE + head repack (validated in R3) -----------------------
__global__ void pack_qk(const int* __restrict__ pos) {
    int idx = blockIdx.x * blockDim.x + threadIdx.x;
    if (idx >= MTOK * 384) return;
    int p = idx % 384;
    int m = idx / 384;
    int s = m & (S_ - 1);
    int b = m >> 11;
    size_t nb = (size_t)m * 768;
    {   // nope pair -> heads 0-5
        int c = 2 * p;
        int h = c >> 7, d = c & 127;
        size_t ob = ((size_t)(b * H_ + h) * S_ + s) * DQK + d;
        g_q[ob]     = g_qnope[nb + c];
        g_q[ob + 1] = g_qnope[nb + c + 1];
        g_k[ob]     = g_knope[nb + c];
        g_k[ob + 1] = g_knope[nb + c + 1];
    }
    {   // rope pair -> heads 6-11, freq over full 768-dim vector
        float inv_freq = powf(10000.0f, -(float)(2 * p) / 768.0f);
        float ang = (float)pos[s] * inv_freq;
        float sn, cs;
        sincosf(ang, &sn, &cs);
        int e = 2 * p;
        int h = 6 + (e >> 7), d = e & 127;
        size_t ob = ((size_t)(b * H_ + h) * S_ + s) * DQK + d;
        float qe = g_qrope[nb + e], qo = g_qrope[nb + e + 1];
        g_q[ob]     = qe * cs - qo * sn;
        g_q[ob + 1] = qe * sn + qo * cs;
        float ke = g_krope[nb + e], ko = g_krope[nb + e + 1];
        g_k[ob]     = ke * cs - ko * sn;
        g_k[ob + 1] = ke * sn + ko * cs;
    }
}

// ---------------- flash attention with tf32 mma (R5-passing layout) ----------
// CTA: 64 q-rows, 8 warps = 4 (q-row groups of 16) x 2 (wc).
// QK: warp computes 16 rows x 32 keys.  PV: 16 rows x 64 d-cols.
#define KSTR 132
#define PSTR 68
#define ATT_SMEM ((64*KSTR*2 + 64*PSTR + 128) * 4)

__global__ __launch_bounds__(256, 1) void attn_mma() {
    extern __shared__ float sm[];
    float* Ks = sm;
    float* Vs = Ks + 64 * KSTR;
    float* Ps = Vs + 64 * KSTR;
    float* Al = Ps + 64 * PSTR;
    float* Li = Al + 64;
    const int qt = gridDim.x - 1 - blockIdx.x;   // big causal tiles first
    const int bh = blockIdx.y;
    const int b = bh / H_, h = bh % H_;
    const int tid = threadIdx.x, lane = tid & 31, wid = tid >> 5;
    const int wr = wid >> 1, wc = wid & 1;
    const int g = lane >> 2, t4 = lane & 3;
    const float scale = 0.0883883476483184f;   // 1/sqrt(128)

    unsigned qa[16][4];
    const float* qb = g_q + ((size_t)bh * S_ + qt * 64 + wr * 16) * DQK;
    #pragma unroll
    for (int ks = 0; ks < 16; ++ks) {
        qa[ks][0] = f2tf(qb[(size_t)g * DQK + ks * 8 + t4]);
        qa[ks][1] = f2tf(qb[(size_t)(g + 8) * DQK + ks * 8 + t4]);
        qa[ks][2] = f2tf(qb[(size_t)g * DQK + ks * 8 + t4 + 4]);
        qa[ks][3] = f2tf(qb[(size_t)(g + 8) * DQK + ks * 8 + t4 + 4]);
    }

    float oc[8][4];
    #pragma unroll
    for (int i = 0; i < 8; ++i)
        #pragma unroll
        for (int j = 0; j < 4; ++j) oc[i][j] = 0.f;

    const int rs = tid >> 2, ln = tid & 3;
    float m_i = -INFINITY, l_i = 0.f;

    const float* kg = g_k + (size_t)bh * S_ * DQK;
    const float* vg = g_v + (size_t)b * S_ * (H_ * DV) + h * DV;

    for (int t = 0; t <= qt; ++t) {
        __syncthreads();
        for (int i = tid; i < 2048; i += 256) {
            int rr = i >> 5, d4 = (i & 31) << 2;
            float4 kv = *(const float4*)(kg + (size_t)(t * 64 + rr) * DQK + d4);
            float* pk = Ks + rr * KSTR + d4;
            pk[0] = __uint_as_float(f2tf(kv.x));
            pk[1] = __uint_as_float(f2tf(kv.y));
            pk[2] = __uint_as_float(f2tf(kv.z));
            pk[3] = __uint_as_float(f2tf(kv.w));
            float4 vv = *(const float4*)(vg + (size_t)(t * 64 + rr) * (H_*DV) + d4);
            float* pv = Vs + rr * KSTR + d4;
            pv[0] = __uint_as_float(f2tf(vv.x));
            pv[1] = __uint_as_float(f2tf(vv.y));
            pv[2] = __uint_as_float(f2tf(vv.z));
            pv[3] = __uint_as_float(f2tf(vv.w));
        }
        __syncthreads();

        float sc[4][4];
        #pragma unroll
        for (int i = 0; i < 4; ++i)
            #pragma unroll
            for (int j = 0; j < 4; ++j) sc[i][j] = 0.f;
        #pragma unroll
        for (int ks = 0; ks < 16; ++ks) {
            #pragma unroll
            for (int nf = 0; nf < 4; ++nf) {
                unsigned kb[2];
                int key = wc * 32 + nf * 8 + g;
                kb[0] = __float_as_uint(Ks[key * KSTR + ks * 8 + t4]);
                kb[1] = __float_as_uint(Ks[key * KSTR + ks * 8 + t4 + 4]);
                mma8(sc[nf], qa[ks], kb);
            }
        }
        const bool diag = (t == qt);
        #pragma unroll
        for (int nf = 0; nf < 4; ++nf) {
            int kl = wc * 32 + nf * 8 + 2 * t4;
            int rl = wr * 16 + g;
            int kgl = t * 64 + kl;
            int rgl = qt * 64 + rl;
            float v0 = sc[nf][0] * scale, v1 = sc[nf][1] * scale;
            float v2 = sc[nf][2] * scale, v3 = sc[nf][3] * scale;
            if (diag) {
                if (kgl     > rgl)     v0 = -1e30f;
                if (kgl + 1 > rgl)     v1 = -1e30f;
                if (kgl     > rgl + 8) v2 = -1e30f;
                if (kgl + 1 > rgl + 8) v3 = -1e30f;
            }
            Ps[rl * PSTR + kl]           = v0;
            Ps[rl * PSTR + kl + 1]       = v1;
            Ps[(rl + 8) * PSTR + kl]     = v2;
            Ps[(rl + 8) * PSTR + kl + 1] = v3;
        }
        __syncthreads();

        float pv[16];
        float mloc = -1e30f;
        #pragma unroll
        for (int j4 = 0; j4 < 4; ++j4) {
            float4 v = *(const float4*)(Ps + rs * PSTR + ln * 16 + 4 * j4);
            pv[4*j4] = v.x; pv[4*j4+1] = v.y; pv[4*j4+2] = v.z; pv[4*j4+3] = v.w;
            mloc = fmaxf(mloc, fmaxf(fmaxf(v.x, v.y), fmaxf(v.z, v.w)));
        }
        mloc = fmaxf(mloc, __shfl_xor_sync(0xffffffffu, mloc, 1));
        mloc = fmaxf(mloc, __shfl_xor_sync(0xffffffffu, mloc, 2));
        float m_new = fmaxf(m_i, mloc);
        float alpha = __expf(m_i - m_new);
        float lsum = 0.f;
        #pragma unroll
        for (int j4 = 0; j4 < 4; ++j4) {
            float4 o4;
            float p0 = __expf(pv[4*j4]   - m_new);
            float p1 = __expf(pv[4*j4+1] - m_new);
            float p2 = __expf(pv[4*j4+2] - m_new);
            float p3 = __expf(pv[4*j4+3] - m_new);
            lsum += (p0 + p1) + (p2 + p3);
            o4.x = __uint_as_float(f2tf(p0));
            o4.y = __uint_as_float(f2tf(p1));
            o4.z = __uint_as_float(f2tf(p2));
            o4.w = __uint_as_float(f2tf(p3));
            *(float4*)(Ps + rs * PSTR + ln * 16 + 4 * j4) = o4;
        }
        lsum += __shfl_xor_sync(0xffffffffu, lsum, 1);
        lsum += __shfl_xor_sync(0xffffffffu, lsum, 2);
        l_i = l_i * alpha + lsum;
        m_i = m_new;
        if (ln == 0) Al[rs] = alpha;
        __syncthreads();

        float a0 = Al[wr * 16 + g], a1 = Al[wr * 16 + g + 8];
        #pragma unroll
        for (int nf = 0; nf < 8; ++nf) {
            oc[nf][0] *= a0; oc[nf][1] *= a0;
            oc[nf][2] *= a1; oc[nf][3] *= a1;
        }
        #pragma unroll
        for (int ks = 0; ks < 8; ++ks) {
            unsigned pa[4];
            int rl = wr * 16 + g;
            pa[0] = __float_as_uint(Ps[rl * PSTR + ks * 8 + t4]);
            pa[1] = __float_as_uint(Ps[(rl + 8) * PSTR + ks * 8 + t4]);
            pa[2] = __float_as_uint(Ps[rl * PSTR + ks * 8 + t4 + 4]);
            pa[3] = __float_as_uint(Ps[(rl + 8) * PSTR + ks * 8 + t4 + 4]);
            #pragma unroll
            for (int nf = 0; nf < 8; ++nf) {
                unsigned vb[2];
                int dcol = wc * 64 + nf * 8 + g;
                vb[0] = __float_as_uint(Vs[(ks * 8 + t4) * KSTR + dcol]);
                vb[1] = __float_as_uint(Vs[(ks * 8 + t4 + 4) * KSTR + dcol]);
                mma8(oc[nf], pa, vb);
            }
        }
    }
    if (ln == 0) Li[rs] = 1.0f / l_i;
    __syncthreads();
    float li0 = Li[wr * 16 + g], li1 = Li[wr * 16 + g + 8];
    int rg = qt * 64 + wr * 16 + g;
    #pragma unroll
    for (int nf = 0; nf < 8; ++nf) {
        int dcol = wc * 64 + nf * 8 + 2 * t4;
        float* o0 = g_o + ((size_t)(b * S_) + rg) * (H_ * DV) + h * DV + dcol;
        float* o1 = o0 + 8 * (size_t)(H_ * DV);
        o0[0] = oc[nf][0] * li0; o0[1] = oc[nf][1] * li0;
        o1[0] = oc[nf][2] * li1; o1[1] = oc[nf][3] * li1;
    }
}

// ---------------- launcher ---------------------------------------------------
extern "C" void kernel_launch(void* const* d_in, const int* in_sizes, int n_in,
                              void* d_out, int out_size) {
    const float* x         = (const float*)d_in[0];
    const int*   pos       = (const int*)  d_in[1];
    const float* W_dkv     = (const float*)d_in[2];
    const float* b_dkv     = (const float*)d_in[3];
    const float* W_dq      = (const float*)d_in[4];
    const float* b_dq      = (const float*)d_in[5];
    const float* W_uk_nope = (const float*)d_in[6];
    const float* b_uk_nope = (const float*)d_in[7];
    const float* W_uv      = (const float*)d_in[8];
    const float* b_uv      = (const float*)d_in[9];
    const float* W_uq_nope = (const float*)d_in[10];
    const float* b_uq_nope = (const float*)d_in[11];
    const float* W_uq_rope = (const float*)d_in[12];
    const float* b_uq_rope = (const float*)d_in[13];
    const float* W_uk_rope = (const float*)d_in[14];
    const float* b_uk_rope = (const float*)d_in[15];
    const float* W_o       = (const float*)d_in[16];
    const float* b_o       = (const float*)d_in[17];
    float* out = (float*)d_out;

    float *Ckv, *Cq, *qn, *qr, *kn, *kr, *v, *o;
    cudaGetSymbolAddress((void**)&Ckv, g_Ckv);
    cudaGetSymbolAddress((void**)&Cq,  g_Cq);
    cudaGetSymbolAddress((void**)&qn,  g_qnope);
    cudaGetSymbolAddress((void**)&qr,  g_qrope);
    cudaGetSymbolAddress((void**)&kn,  g_knope);
    cudaGetSymbolAddress((void**)&kr,  g_krope);
    cudaGetSymbolAddress((void**)&v,   g_v);
    cudaGetSymbolAddress((void**)&o,   g_o);

    auto launch2 = [&](GemmJob a, GemmJob b) {
        int nmax = a.N > b.N ? a.N : b.N;
        dim3 grid(nmax / 128, MTOK / 128, 2);
        gemm_tf32_dual<<<grid, 256>>>(a, b);
    };
    auto launch1 = [&](GemmJob a) {
        dim3 grid(a.N / 128, MTOK / 128, 1);
        gemm_tf32_dual<<<grid, 256>>>(a, a);
    };

    // #1: dkv + dq (A = x)
    launch2({x, W_dkv, b_dkv, Ckv, DL, DM}, {x, W_dq, b_dq, Cq, DL, DM});
    // #2: uk_rope (A = x)
    launch1({x, W_uk_rope, b_uk_rope, kr, H_*64, DM});
    // #3: uq_nope + uq_rope (A = Cq)
    launch2({Cq, W_uq_nope, b_uq_nope, qn, H_*64, DL},
            {Cq, W_uq_rope, b_uq_rope, qr, H_*64, DL});
    // #4: uk_nope + uv (A = Ckv)
    launch2({Ckv, W_uk_nope, b_uk_nope, kn, H_*64, DL},
            {Ckv, W_uv, b_uv, v, H_*DV, DL});
    // #5: pack/rope
    int packTotal = MTOK * 384;
    pack_qk<<<(packTotal + 255) / 256, 256>>>(pos);
    // #6: attention  (profiled by ncu -s 5 -c 1)
    cudaFuncSetAttribute(attn_mma, cudaFuncAttributeMaxDynamicSharedMemorySize,
                         ATT_SMEM);
    attn_mma<<<dim3(S_ / 64, B_ * H_), 256, ATT_SMEM>>>();
    // #7: output projection
    launch1({o, W_o, b_o, out, DM, H_*DV});
}

// round 8
// speedup vs baseline: 4.4305x; 1.1685x over previous
#include <cuda_runtime.h>
#include <math.h>

#define B_   4
#define S_   2048
#define H_   12
#define DM   768
#define DL   128
#define DQK  128
#define DV   128
#define MTOK (B_*S_)   // 8192

// ---------------- scratch ----------------------------------------------------
__device__ float g_Ckv  [MTOK*DL];
__device__ float g_Cq   [MTOK*DL];
__device__ float g_qnope[MTOK*H_*64];
__device__ float g_qrope[MTOK*H_*64];
__device__ float g_knope[MTOK*H_*64];
__device__ float g_krope[MTOK*H_*64];
__device__ float g_v    [MTOK*H_*DV];                 // (b,s,h,dv)
__device__ float g_q    [B_*H_*S_*DQK];               // (b*h, s, d)
__device__ float g_k    [B_*H_*S_*DQK];
__device__ float g_o    [MTOK*H_*DV];                 // (b,s,h,dv)

// ---------------- tf32 helpers ----------------------------------------------
__device__ __forceinline__ unsigned f2tf(float x) {
    unsigned r; asm("cvt.rna.tf32.f32 %0, %1;" : "=r"(r) : "f"(x)); return r;
}
__device__ __forceinline__ float f2tff(float x) {
    return __uint_as_float(f2tf(x));
}
__device__ __forceinline__ void mma8(float* d, const unsigned* a,
                                     const unsigned* b) {
    asm volatile(
        "mma.sync.aligned.m16n8k8.row.col.f32.tf32.tf32.f32 "
        "{%0,%1,%2,%3}, {%4,%5,%6,%7}, {%8,%9}, {%0,%1,%2,%3};"
        : "+f"(d[0]), "+f"(d[1]), "+f"(d[2]), "+f"(d[3])
        : "r"(a[0]), "r"(a[1]), "r"(a[2]), "r"(a[3]), "r"(b[0]), "r"(b[1]));
}

// ---------------- tf32 GEMM (dual-job, unchanged from R7 pass) ---------------
struct GemmJob {
    const float* A; const float* W; const float* bias; float* C;
    int N; int K;
};

#define GSTR 20
__global__ __launch_bounds__(256) void gemm_tf32_dual(GemmJob j0, GemmJob j1) {
    const GemmJob j = blockIdx.z ? j1 : j0;
    const int N = j.N, K = j.K;
    const int n0 = blockIdx.x << 7;
    if (n0 >= N) return;
    const float* __restrict__ A = j.A;
    const float* __restrict__ W = j.W;
    __shared__ float As[128 * GSTR];
    __shared__ float Ws[128 * GSTR];
    const int tid = threadIdx.x, lane = tid & 31, wid = tid >> 5;
    const int m0 = blockIdx.y << 7;
    const int wm = wid & 1, wn = wid >> 1;
    const int g  = lane >> 2, t4 = lane & 3;
    float acc[4][4][4];
    #pragma unroll
    for (int i = 0; i < 4; ++i)
        #pragma unroll
        for (int jj = 0; jj < 4; ++jj)
            #pragma unroll
            for (int e = 0; e < 4; ++e) acc[i][jj][e] = 0.f;

    const int lrow0 = tid >> 2, lcol = (tid & 3) << 2;
    float4 ar[2], wr_[2];
    {
        ar[0]  = *(const float4*)(A + (size_t)(m0 + lrow0) * K + lcol);
        ar[1]  = *(const float4*)(A + (size_t)(m0 + lrow0 + 64) * K + lcol);
        wr_[0] = *(const float4*)(W + (size_t)(n0 + lrow0) * K + lcol);
        wr_[1] = *(const float4*)(W + (size_t)(n0 + lrow0 + 64) * K + lcol);
    }
    for (int k0 = 0; k0 < K; k0 += 16) {
        __syncthreads();
        #pragma unroll
        for (int jj = 0; jj < 2; ++jj) {
            int row = lrow0 + jj * 64;
            float* pa = As + row * GSTR + lcol;
            pa[0] = f2tff(ar[jj].x); pa[1] = f2tff(ar[jj].y);
            pa[2] = f2tff(ar[jj].z); pa[3] = f2tff(ar[jj].w);
            float* pw = Ws + row * GSTR + lcol;
            pw[0] = f2tff(wr_[jj].x); pw[1] = f2tff(wr_[jj].y);
            pw[2] = f2tff(wr_[jj].z); pw[3] = f2tff(wr_[jj].w);
        }
        __syncthreads();
        if (k0 + 16 < K) {
            int kc = k0 + 16 + lcol;
            ar[0]  = *(const float4*)(A + (size_t)(m0 + lrow0) * K + kc);
            ar[1]  = *(const float4*)(A + (size_t)(m0 + lrow0 + 64) * K + kc);
            wr_[0] = *(const float4*)(W + (size_t)(n0 + lrow0) * K + kc);
            wr_[1] = *(const float4*)(W + (size_t)(n0 + lrow0 + 64) * K + kc);
        }
        #pragma unroll
        for (int ks = 0; ks < 2; ++ks) {
            unsigned af[4][4], bf[4][2];
            #pragma unroll
            for (int mf = 0; mf < 4; ++mf) {
                int row = wm * 64 + mf * 16 + g;
                int col = ks * 8 + t4;
                af[mf][0] = __float_as_uint(As[row * GSTR + col]);
                af[mf][1] = __float_as_uint(As[(row + 8) * GSTR + col]);
                af[mf][2] = __float_as_uint(As[row * GSTR + col + 4]);
                af[mf][3] = __float_as_uint(As[(row + 8) * GSTR + col + 4]);
            }
            #pragma unroll
            for (int nf = 0; nf < 4; ++nf) {
                int n = wn * 32 + nf * 8 + g;
                int kk = ks * 8 + t4;
                bf[nf][0] = __float_as_uint(Ws[n * GSTR + kk]);
                bf[nf][1] = __float_as_uint(Ws[n * GSTR + kk + 4]);
            }
            #pragma unroll
            for (int mf = 0; mf < 4; ++mf)
                #pragma unroll
                for (int nf = 0; nf < 4; ++nf)
                    mma8(acc[mf][nf], af[mf], bf[nf]);
        }
    }
    #pragma unroll
    for (int mf = 0; mf < 4; ++mf) {
        int row = m0 + wm * 64 + mf * 16 + g;
        #pragma unroll
        for (int nf = 0; nf < 4; ++nf) {
            int col = n0 + wn * 32 + nf * 8 + 2 * t4;
            float b0 = j.bias[col], b1 = j.bias[col + 1];
            j.C[(size_t)row * N + col]           = acc[mf][nf][0] + b0;
            j.C[(size_t)row * N + col + 1]       = acc[mf][nf][1] + b1;
            j.C[(size_t)(row + 8) * N + col]     = acc[mf][nf][2] + b0;
            j.C[(size_t)(row + 8) * N + col + 1] = acc[mf][nf][3] + b1;
        }
    }
}

// ---------------- RoPE + head repack (validated in R3) -----------------------
__global__ void pack_qk(const int* __restrict__ pos) {
    int idx = blockIdx.x * blockDim.x + threadIdx.x;
    if (idx >= MTOK * 384) return;
    int p = idx % 384;
    int m = idx / 384;
    int s = m & (S_ - 1);
    int b = m >> 11;
    size_t nb = (size_t)m * 768;
    {   // nope pair -> heads 0-5
        int c = 2 * p;
        int h = c >> 7, d = c & 127;
        size_t ob = ((size_t)(b * H_ + h) * S_ + s) * DQK + d;
        g_q[ob]     = g_qnope[nb + c];
        g_q[ob + 1] = g_qnope[nb + c + 1];
        g_k[ob]     = g_knope[nb + c];
        g_k[ob + 1] = g_knope[nb + c + 1];
    }
    {   // rope pair -> heads 6-11, freq over full 768-dim vector
        float inv_freq = powf(10000.0f, -(float)(2 * p) / 768.0f);
        float ang = (float)pos[s] * inv_freq;
        float sn, cs;
        sincosf(ang, &sn, &cs);
        int e = 2 * p;
        int h = 6 + (e >> 7), d = e & 127;
        size_t ob = ((size_t)(b * H_ + h) * S_ + s) * DQK + d;
        float qe = g_qrope[nb + e], qo = g_qrope[nb + e + 1];
        g_q[ob]     = qe * cs - qo * sn;
        g_q[ob + 1] = qe * sn + qo * cs;
        float ke = g_krope[nb + e], ko = g_krope[nb + e + 1];
        g_k[ob]     = ke * cs - ko * sn;
        g_k[ob + 1] = ke * sn + ko * cs;
    }
}

// ---------------- flash attention v2: register-resident P --------------------
// q-tile 128, 8 warps x 16 rows, each warp covers all 64 keys and all 128
// d-cols of its rows. Softmax on mma C-frags in registers (shfl row-reduce).
// C-frag -> A-frag conversion for PV via 8 shuffles per k8-step.
// K/V double-buffered in smem with register prefetch; ONE barrier per k-tile.
#define QSTR 132
#define KSTR 132
#define ATT_SMEM ((128*QSTR + 4*64*KSTR) * 4)   // 202752 bytes

__global__ __launch_bounds__(256, 1) void attn_mma() {
    extern __shared__ float sm[];
    float* Qs  = sm;
    float* Kb0 = sm + 128 * QSTR;
    float* Kb1 = Kb0 + 64 * KSTR;
    float* Vb0 = Kb1 + 64 * KSTR;
    float* Vb1 = Vb0 + 64 * KSTR;
    const int qt = gridDim.x - 1 - blockIdx.x;   // big causal tiles first
    const int bh = blockIdx.y;
    const int b = bh / H_, h = bh % H_;
    const int tid = threadIdx.x, lane = tid & 31, wid = tid >> 5;
    const int g = lane >> 2, t4 = lane & 3;
    const float scale = 0.0883883476483184f;     // 1/sqrt(128)

    // stage Q tile (scale folded in)
    const float* qg = g_q + ((size_t)bh * S_ + qt * 128) * DQK;
    for (int i = tid; i < 4096; i += 256) {
        int rr = i >> 5, c4 = (i & 31) << 2;
        float4 qv = *(const float4*)(qg + (size_t)rr * DQK + c4);
        float* p = Qs + rr * QSTR + c4;
        p[0] = f2tff(qv.x * scale); p[1] = f2tff(qv.y * scale);
        p[2] = f2tff(qv.z * scale); p[3] = f2tff(qv.w * scale);
    }

    const float* kg = g_k + (size_t)bh * S_ * DQK;
    const float* vg = g_v + (size_t)(b * S_) * (H_ * DV) + h * DV;
    const int nt = 2 * qt + 2;

    // prefetch tile 0 into registers
    float4 kf[8], vf[8];
    #pragma unroll
    for (int jj = 0; jj < 8; ++jj) {
        int idx = tid + jj * 256;
        int rr = idx >> 5, c4 = (idx & 31) << 2;
        kf[jj] = *(const float4*)(kg + (size_t)rr * DQK + c4);
        vf[jj] = *(const float4*)(vg + (size_t)rr * (H_ * DV) + c4);
    }

    float oc[16][4];
    #pragma unroll
    for (int i = 0; i < 16; ++i)
        #pragma unroll
        for (int e = 0; e < 4; ++e) oc[i][e] = 0.f;

    float m0 = -1e30f, m1 = -1e30f, l0 = 0.f, l1 = 0.f;
    const int r0l  = wid * 16 + g;        // local q row (of 128)
    const int r0gl = qt * 128 + r0l;      // global q row

    for (int t = 0; t < nt; ++t) {
        float* Kd = (t & 1) ? Kb1 : Kb0;
        float* Vd = (t & 1) ? Vb1 : Vb0;
        // store prefetched tile into this buffer
        #pragma unroll
        for (int jj = 0; jj < 8; ++jj) {
            int idx = tid + jj * 256;
            int rr = idx >> 5, c4 = (idx & 31) << 2;
            float* pk = Kd + rr * KSTR + c4;
            pk[0] = f2tff(kf[jj].x); pk[1] = f2tff(kf[jj].y);
            pk[2] = f2tff(kf[jj].z); pk[3] = f2tff(kf[jj].w);
            float* pv = Vd + rr * KSTR + c4;
            pv[0] = f2tff(vf[jj].x); pv[1] = f2tff(vf[jj].y);
            pv[2] = f2tff(vf[jj].z); pv[3] = f2tff(vf[jj].w);
        }
        __syncthreads();
        // prefetch next tile (overlaps compute below)
        if (t + 1 < nt) {
            const float* kgn = kg + (size_t)(t + 1) * 64 * DQK;
            const float* vgn = vg + (size_t)(t + 1) * 64 * (H_ * DV);
            #pragma unroll
            for (int jj = 0; jj < 8; ++jj) {
                int idx = tid + jj * 256;
                int rr = idx >> 5, c4 = (idx & 31) << 2;
                kf[jj] = *(const float4*)(kgn + (size_t)rr * DQK + c4);
                vf[jj] = *(const float4*)(vgn + (size_t)rr * (H_ * DV) + c4);
            }
        }

        // ---- S = Q K^T : warp computes its 16 rows x 64 keys -------------
        float sc[8][4];
        #pragma unroll
        for (int i = 0; i < 8; ++i)
            #pragma unroll
            for (int e = 0; e < 4; ++e) sc[i][e] = 0.f;
        #pragma unroll
        for (int ks = 0; ks < 16; ++ks) {
            unsigned aq[4];
            const float* qr = Qs + r0l * QSTR + ks * 8 + t4;
            aq[0] = __float_as_uint(qr[0]);
            aq[1] = __float_as_uint(qr[8 * QSTR]);
            aq[2] = __float_as_uint(qr[4]);
            aq[3] = __float_as_uint(qr[8 * QSTR + 4]);
            #pragma unroll
            for (int nf = 0; nf < 8; ++nf) {
                unsigned kb2[2];
                const float* kr = Kd + (nf * 8 + g) * KSTR + ks * 8 + t4;
                kb2[0] = __float_as_uint(kr[0]);
                kb2[1] = __float_as_uint(kr[4]);
                mma8(sc[nf], aq, kb2);
            }
        }
        // ---- causal mask (only the two diagonal-overlapping tiles) -------
        if (t >= 2 * qt) {
            #pragma unroll
            for (int nf = 0; nf < 8; ++nf) {
                int k0 = t * 64 + nf * 8 + 2 * t4;
                if (k0     > r0gl)     sc[nf][0] = -1e30f;
                if (k0 + 1 > r0gl)     sc[nf][1] = -1e30f;
                if (k0     > r0gl + 8) sc[nf][2] = -1e30f;
                if (k0 + 1 > r0gl + 8) sc[nf][3] = -1e30f;
            }
        }
        // ---- online softmax on register fragments ------------------------
        float ml0 = -1e30f, ml1 = -1e30f;
        #pragma unroll
        for (int nf = 0; nf < 8; ++nf) {
            ml0 = fmaxf(ml0, fmaxf(sc[nf][0], sc[nf][1]));
            ml1 = fmaxf(ml1, fmaxf(sc[nf][2], sc[nf][3]));
        }
        ml0 = fmaxf(ml0, __shfl_xor_sync(0xffffffffu, ml0, 1));
        ml0 = fmaxf(ml0, __shfl_xor_sync(0xffffffffu, ml0, 2));
        ml1 = fmaxf(ml1, __shfl_xor_sync(0xffffffffu, ml1, 1));
        ml1 = fmaxf(ml1, __shfl_xor_sync(0xffffffffu, ml1, 2));
        float mn0 = fmaxf(m0, ml0), mn1 = fmaxf(m1, ml1);
        float a0 = __expf(m0 - mn0), a1 = __expf(m1 - mn1);
        float s0 = 0.f, s1 = 0.f;
        #pragma unroll
        for (int nf = 0; nf < 8; ++nf) {
            float p00 = __expf(sc[nf][0] - mn0);
            float p01 = __expf(sc[nf][1] - mn0);
            float p10 = __expf(sc[nf][2] - mn1);
            float p11 = __expf(sc[nf][3] - mn1);
            s0 += p00 + p01; s1 += p10 + p11;
            sc[nf][0] = f2tff(p00); sc[nf][1] = f2tff(p01);
            sc[nf][2] = f2tff(p10); sc[nf][3] = f2tff(p11);
        }
        s0 += __shfl_xor_sync(0xffffffffu, s0, 1);
        s0 += __shfl_xor_sync(0xffffffffu, s0, 2);
        s1 += __shfl_xor_sync(0xffffffffu, s1, 1);
        s1 += __shfl_xor_sync(0xffffffffu, s1, 2);
        l0 = l0 * a0 + s0; l1 = l1 * a1 + s1;
        m0 = mn0; m1 = mn1;
        #pragma unroll
        for (int nf = 0; nf < 16; ++nf) {
            oc[nf][0] *= a0; oc[nf][1] *= a0;
            oc[nf][2] *= a1; oc[nf][3] *= a1;
        }
        // ---- O += P V : C-frag -> A-frag via shfl, then mma --------------
        const int srcA = (lane & ~3) | (t4 >> 1);
        const bool odd = (t4 & 1);
        #pragma unroll
        for (int ks = 0; ks < 8; ++ks) {
            float e0A = __shfl_sync(0xffffffffu, sc[ks][0], srcA);
            float e1A = __shfl_sync(0xffffffffu, sc[ks][1], srcA);
            float e2A = __shfl_sync(0xffffffffu, sc[ks][2], srcA);
            float e3A = __shfl_sync(0xffffffffu, sc[ks][3], srcA);
            float e0B = __shfl_sync(0xffffffffu, sc[ks][0], srcA + 2);
            float e1B = __shfl_sync(0xffffffffu, sc[ks][1], srcA + 2);
            float e2B = __shfl_sync(0xffffffffu, sc[ks][2], srcA + 2);
            float e3B = __shfl_sync(0xffffffffu, sc[ks][3], srcA + 2);
            unsigned pa[4];
            pa[0] = __float_as_uint(odd ? e1A : e0A);
            pa[1] = __float_as_uint(odd ? e3A : e2A);
            pa[2] = __float_as_uint(odd ? e1B : e0B);
            pa[3] = __float_as_uint(odd ? e3B : e2B);
            #pragma unroll
            for (int nf = 0; nf < 16; ++nf) {
                unsigned vb2[2];
                const float* vr = Vd + (ks * 8 + t4) * KSTR + nf * 8 + g;
                vb2[0] = __float_as_uint(vr[0]);
                vb2[1] = __float_as_uint(vr[4 * KSTR]);
                mma8(oc[nf], pa, vb2);
            }
        }
    }
    // ---- epilogue -------------------------------------------------------
    float il0 = 1.0f / l0, il1 = 1.0f / l1;
    float* ob = g_o + ((size_t)(b * S_) + r0gl) * (H_ * DV) + h * DV;
    float* ob1 = ob + 8 * (size_t)(H_ * DV);
    #pragma unroll
    for (int nf = 0; nf < 16; ++nf) {
        int col = nf * 8 + 2 * t4;
        float2 v0 = make_float2(oc[nf][0] * il0, oc[nf][1] * il0);
        *(float2*)(ob + col) = v0;
        float2 v1 = make_float2(oc[nf][2] * il1, oc[nf][3] * il1);
        *(float2*)(ob1 + col) = v1;
    }
}

// ---------------- launcher ---------------------------------------------------
extern "C" void kernel_launch(void* const* d_in, const int* in_sizes, int n_in,
                              void* d_out, int out_size) {
    const float* x         = (const float*)d_in[0];
    const int*   pos       = (const int*)  d_in[1];
    const float* W_dkv     = (const float*)d_in[2];
    const float* b_dkv     = (const float*)d_in[3];
    const float* W_dq      = (const float*)d_in[4];
    const float* b_dq      = (const float*)d_in[5];
    const float* W_uk_nope = (const float*)d_in[6];
    const float* b_uk_nope = (const float*)d_in[7];
    const float* W_uv      = (const float*)d_in[8];
    const float* b_uv      = (const float*)d_in[9];
    const float* W_uq_nope = (const float*)d_in[10];
    const float* b_uq_nope = (const float*)d_in[11];
    const float* W_uq_rope = (const float*)d_in[12];
    const float* b_uq_rope = (const float*)d_in[13];
    const float* W_uk_rope = (const float*)d_in[14];
    const float* b_uk_rope = (const float*)d_in[15];
    const float* W_o       = (const float*)d_in[16];
    const float* b_o       = (const float*)d_in[17];
    float* out = (float*)d_out;

    float *Ckv, *Cq, *qn, *qr, *kn, *kr, *v, *o;
    cudaGetSymbolAddress((void**)&Ckv, g_Ckv);
    cudaGetSymbolAddress((void**)&Cq,  g_Cq);
    cudaGetSymbolAddress((void**)&qn,  g_qnope);
    cudaGetSymbolAddress((void**)&qr,  g_qrope);
    cudaGetSymbolAddress((void**)&kn,  g_knope);
    cudaGetSymbolAddress((void**)&kr,  g_krope);
    cudaGetSymbolAddress((void**)&v,   g_v);
    cudaGetSymbolAddress((void**)&o,   g_o);

    auto launch2 = [&](GemmJob a, GemmJob b) {
        int nmax = a.N > b.N ? a.N : b.N;
        dim3 grid(nmax / 128, MTOK / 128, 2);
        gemm_tf32_dual<<<grid, 256>>>(a, b);
    };
    auto launch1 = [&](GemmJob a) {
        dim3 grid(a.N / 128, MTOK / 128, 1);
        gemm_tf32_dual<<<grid, 256>>>(a, a);
    };

    // #1: dkv + dq (A = x)
    launch2({x, W_dkv, b_dkv, Ckv, DL, DM}, {x, W_dq, b_dq, Cq, DL, DM});
    // #2: uk_rope (A = x)
    launch1({x, W_uk_rope, b_uk_rope, kr, H_*64, DM});
    // #3: uq_nope + uq_rope (A = Cq)
    launch2({Cq, W_uq_nope, b_uq_nope, qn, H_*64, DL},
            {Cq, W_uq_rope, b_uq_rope, qr, H_*64, DL});
    // #4: uk_nope + uv (A = Ckv)
    launch2({Ckv, W_uk_nope, b_uk_nope, kn, H_*64, DL},
            {Ckv, W_uv, b_uv, v, H_*DV, DL});
    // #5: pack/rope
    int packTotal = MTOK * 384;
    pack_qk<<<(packTotal + 255) / 256, 256>>>(pos);
    // #6: attention (q-tile 128)
    cudaFuncSetAttribute(attn_mma, cudaFuncAttributeMaxDynamicSharedMemorySize,
                         ATT_SMEM);
    attn_mma<<<dim3(S_ / 128, B_ * H_), 256, ATT_SMEM>>>();
    // #7: output projection
    launch1({o, W_o, b_o, out, DM, H_*DV});
}

// round 9
// speedup vs baseline: 4.6293x; 1.0449x over previous
#include <cuda_runtime.h>
#include <math.h>

#define B_   4
#define S_   2048
#define H_   12
#define DM   768
#define DL   128
#define DQK  128
#define DV   128
#define MTOK (B_*S_)   // 8192

// ---------------- scratch ----------------------------------------------------
__device__ float g_Ckv  [MTOK*DL];
__device__ float g_Cq   [MTOK*DL];
__device__ float g_qnope[MTOK*H_*64];
__device__ float g_qrope[MTOK*H_*64];
__device__ float g_knope[MTOK*H_*64];
__device__ float g_krope[MTOK*H_*64];
__device__ float g_v    [MTOK*H_*DV];                 // (b,s,h,dv) tf32-rounded
__device__ float g_q    [B_*H_*S_*DQK];               // (b*h,s,d) tf32*scale
__device__ float g_k    [B_*H_*S_*DQK];               // (b*h,s,d) tf32
__device__ float g_o    [MTOK*H_*DV];                 // (b,s,h,dv)

// ---------------- tf32 / cp.async helpers ------------------------------------
__device__ __forceinline__ unsigned f2tf(float x) {
    unsigned r; asm("cvt.rna.tf32.f32 %0, %1;" : "=r"(r) : "f"(x)); return r;
}
__device__ __forceinline__ float f2tff(float x) {
    return __uint_as_float(f2tf(x));
}
__device__ __forceinline__ void mma8(float* d, const unsigned* a,
                                     const unsigned* b) {
    asm volatile(
        "mma.sync.aligned.m16n8k8.row.col.f32.tf32.tf32.f32 "
        "{%0,%1,%2,%3}, {%4,%5,%6,%7}, {%8,%9}, {%0,%1,%2,%3};"
        : "+f"(d[0]), "+f"(d[1]), "+f"(d[2]), "+f"(d[3])
        : "r"(a[0]), "r"(a[1]), "r"(a[2]), "r"(a[3]), "r"(b[0]), "r"(b[1]));
}
__device__ __forceinline__ void cpa16(unsigned dst, const float* src) {
    asm volatile("cp.async.ca.shared.global [%0], [%1], 16;"
                 :: "r"(dst), "l"(src));
}
__device__ __forceinline__ void cpa_commit() {
    asm volatile("cp.async.commit_group;");
}
__device__ __forceinline__ void cpa_wait0() {
    asm volatile("cp.async.wait_group 0;");
}

// ---------------- tf32 GEMM (dual-job) ---------------------------------------
struct GemmJob {
    const float* A; const float* W; const float* bias; float* C;
    int N; int K; int cvt;     // cvt: round output to tf32 (for V)
};

#define GSTR 20
__global__ __launch_bounds__(256) void gemm_tf32_dual(GemmJob j0, GemmJob j1) {
    const GemmJob j = blockIdx.z ? j1 : j0;
    const int N = j.N, K = j.K;
    const int n0 = blockIdx.x << 7;
    if (n0 >= N) return;
    const float* __restrict__ A = j.A;
    const float* __restrict__ W = j.W;
    __shared__ float As[128 * GSTR];
    __shared__ float Ws[128 * GSTR];
    const int tid = threadIdx.x, lane = tid & 31, wid = tid >> 5;
    const int m0 = blockIdx.y << 7;
    const int wm = wid & 1, wn = wid >> 1;
    const int g  = lane >> 2, t4 = lane & 3;
    float acc[4][4][4];
    #pragma unroll
    for (int i = 0; i < 4; ++i)
        #pragma unroll
        for (int jj = 0; jj < 4; ++jj)
            #pragma unroll
            for (int e = 0; e < 4; ++e) acc[i][jj][e] = 0.f;

    const int lrow0 = tid >> 2, lcol = (tid & 3) << 2;
    float4 ar[2], wr_[2];
    {
        ar[0]  = *(const float4*)(A + (size_t)(m0 + lrow0) * K + lcol);
        ar[1]  = *(const float4*)(A + (size_t)(m0 + lrow0 + 64) * K + lcol);
        wr_[0] = *(const float4*)(W + (size_t)(n0 + lrow0) * K + lcol);
        wr_[1] = *(const float4*)(W + (size_t)(n0 + lrow0 + 64) * K + lcol);
    }
    for (int k0 = 0; k0 < K; k0 += 16) {
        __syncthreads();
        #pragma unroll
        for (int jj = 0; jj < 2; ++jj) {
            int row = lrow0 + jj * 64;
            float* pa = As + row * GSTR + lcol;
            pa[0] = f2tff(ar[jj].x); pa[1] = f2tff(ar[jj].y);
            pa[2] = f2tff(ar[jj].z); pa[3] = f2tff(ar[jj].w);
            float* pw = Ws + row * GSTR + lcol;
            pw[0] = f2tff(wr_[jj].x); pw[1] = f2tff(wr_[jj].y);
            pw[2] = f2tff(wr_[jj].z); pw[3] = f2tff(wr_[jj].w);
        }
        __syncthreads();
        if (k0 + 16 < K) {
            int kc = k0 + 16 + lcol;
            ar[0]  = *(const float4*)(A + (size_t)(m0 + lrow0) * K + kc);
            ar[1]  = *(const float4*)(A + (size_t)(m0 + lrow0 + 64) * K + kc);
            wr_[0] = *(const float4*)(W + (size_t)(n0 + lrow0) * K + kc);
            wr_[1] = *(const float4*)(W + (size_t)(n0 + lrow0 + 64) * K + kc);
        }
        #pragma unroll
        for (int ks = 0; ks < 2; ++ks) {
            unsigned af[4][4], bf[4][2];
            #pragma unroll
            for (int mf = 0; mf < 4; ++mf) {
                int row = wm * 64 + mf * 16 + g;
                int col = ks * 8 + t4;
                af[mf][0] = __float_as_uint(As[row * GSTR + col]);
                af[mf][1] = __float_as_uint(As[(row + 8) * GSTR + col]);
                af[mf][2] = __float_as_uint(As[row * GSTR + col + 4]);
                af[mf][3] = __float_as_uint(As[(row + 8) * GSTR + col + 4]);
            }
            #pragma unroll
            for (int nf = 0; nf < 4; ++nf) {
                int n = wn * 32 + nf * 8 + g;
                int kk = ks * 8 + t4;
                bf[nf][0] = __float_as_uint(Ws[n * GSTR + kk]);
                bf[nf][1] = __float_as_uint(Ws[n * GSTR + kk + 4]);
            }
            #pragma unroll
            for (int mf = 0; mf < 4; ++mf)
                #pragma unroll
                for (int nf = 0; nf < 4; ++nf)
                    mma8(acc[mf][nf], af[mf], bf[nf]);
        }
    }
    const bool cvt = (j.cvt != 0);
    #pragma unroll
    for (int mf = 0; mf < 4; ++mf) {
        int row = m0 + wm * 64 + mf * 16 + g;
        #pragma unroll
        for (int nf = 0; nf < 4; ++nf) {
            int col = n0 + wn * 32 + nf * 8 + 2 * t4;
            float b0 = j.bias[col], b1 = j.bias[col + 1];
            float r00 = acc[mf][nf][0] + b0, r01 = acc[mf][nf][1] + b1;
            float r10 = acc[mf][nf][2] + b0, r11 = acc[mf][nf][3] + b1;
            if (cvt) { r00 = f2tff(r00); r01 = f2tff(r01);
                       r10 = f2tff(r10); r11 = f2tff(r11); }
            j.C[(size_t)row * N + col]           = r00;
            j.C[(size_t)row * N + col + 1]       = r01;
            j.C[(size_t)(row + 8) * N + col]     = r10;
            j.C[(size_t)(row + 8) * N + col + 1] = r11;
        }
    }
}

// ---------------- RoPE + head repack (tf32 + scale folded at producer) -------
__global__ void pack_qk(const int* __restrict__ pos) {
    int idx = blockIdx.x * blockDim.x + threadIdx.x;
    if (idx >= MTOK * 384) return;
    int p = idx % 384;
    int m = idx / 384;
    int s = m & (S_ - 1);
    int b = m >> 11;
    size_t nb = (size_t)m * 768;
    const float scale = 0.0883883476483184f;   // 1/sqrt(128)
    {   // nope pair -> heads 0-5
        int c = 2 * p;
        int h = c >> 7, d = c & 127;
        size_t ob = ((size_t)(b * H_ + h) * S_ + s) * DQK + d;
        g_q[ob]     = f2tff(g_qnope[nb + c] * scale);
        g_q[ob + 1] = f2tff(g_qnope[nb + c + 1] * scale);
        g_k[ob]     = f2tff(g_knope[nb + c]);
        g_k[ob + 1] = f2tff(g_knope[nb + c + 1]);
    }
    {   // rope pair -> heads 6-11, freq over full 768-dim vector
        float inv_freq = powf(10000.0f, -(float)(2 * p) / 768.0f);
        float ang = (float)pos[s] * inv_freq;
        float sn, cs;
        sincosf(ang, &sn, &cs);
        int e = 2 * p;
        int h = 6 + (e >> 7), d = e & 127;
        size_t ob = ((size_t)(b * H_ + h) * S_ + s) * DQK + d;
        float qe = g_qrope[nb + e], qo = g_qrope[nb + e + 1];
        g_q[ob]     = f2tff((qe * cs - qo * sn) * scale);
        g_q[ob + 1] = f2tff((qe * sn + qo * cs) * scale);
        float ke = g_krope[nb + e], ko = g_krope[nb + e + 1];
        g_k[ob]     = f2tff(ke * cs - ko * sn);
        g_k[ob + 1] = f2tff(ke * sn + ko * cs);
    }
}

// ---------------- flash attention v3: cp.async double buffer -----------------
// q-tile 128, 8 warps x 16 rows; operands pre-rounded to tf32 by producers.
// cp.async gmem->smem, double-buffered K/V, one barrier per k-tile.
#define QSTR 132
#define KSTR 132
#define ATT_SMEM ((128*QSTR + 4*64*KSTR) * 4)   // 202752 bytes

__global__ __launch_bounds__(256, 1) void attn_mma() {
    extern __shared__ float sm[];
    float* Qs = sm;
    const unsigned smb = (unsigned)__cvta_generic_to_shared(sm);
    const unsigned kvb = smb + 128 * QSTR * 4;
    const int qt = gridDim.x - 1 - blockIdx.x;   // big causal tiles first
    const int bh = blockIdx.y;
    const int b = bh / H_, h = bh % H_;
    const int tid = threadIdx.x, lane = tid & 31, wid = tid >> 5;
    const int g = lane >> 2, t4 = lane & 3;

    const float* qg = g_q + ((size_t)bh * S_ + qt * 128) * DQK;
    const float* kg = g_k + (size_t)bh * S_ * DQK;
    const float* vg = g_v + (size_t)(b * S_) * (H_ * DV) + h * DV;
    const int nt = 2 * qt + 2;

    // prologue: Q (16 chunks) + K/V tile 0 (8+8 chunks) in group C0
    #pragma unroll
    for (int jj = 0; jj < 16; ++jj) {
        int idx = tid + jj * 256;
        int rr = idx >> 5, c4 = (idx & 31) << 2;
        cpa16(smb + (rr * QSTR + c4) * 4, qg + (size_t)rr * DQK + c4);
    }
    {
        #pragma unroll
        for (int jj = 0; jj < 8; ++jj) {
            int idx = tid + jj * 256;
            int rr = idx >> 5, c4 = (idx & 31) << 2;
            cpa16(kvb + (rr * KSTR + c4) * 4, kg + (size_t)rr * DQK + c4);
            cpa16(kvb + ((2 * 64 + rr) * KSTR + c4) * 4,
                  vg + (size_t)rr * (H_ * DV) + c4);
        }
        cpa_commit();
    }

    float oc[16][4];
    #pragma unroll
    for (int i = 0; i < 16; ++i)
        #pragma unroll
        for (int e = 0; e < 4; ++e) oc[i][e] = 0.f;

    float m0 = -1e30f, m1 = -1e30f, l0 = 0.f, l1 = 0.f;
    const int r0l  = wid * 16 + g;
    const int r0gl = qt * 128 + r0l;

    for (int t = 0; t < nt; ++t) {
        cpa_wait0();           // tile t (and everything earlier) resident
        __syncthreads();       // visible to all; all done with buffer (t+1)&1
        // issue tile t+1 into the other buffer (overlaps compute below)
        if (t + 1 < nt) {
            int bsel = (t + 1) & 1;
            const float* kgn = kg + (size_t)(t + 1) * 64 * DQK;
            const float* vgn = vg + (size_t)(t + 1) * 64 * (H_ * DV);
            #pragma unroll
            for (int jj = 0; jj < 8; ++jj) {
                int idx = tid + jj * 256;
                int rr = idx >> 5, c4 = (idx & 31) << 2;
                cpa16(kvb + ((bsel * 64 + rr) * KSTR + c4) * 4,
                      kgn + (size_t)rr * DQK + c4);
                cpa16(kvb + (((2 + bsel) * 64 + rr) * KSTR + c4) * 4,
                      vgn + (size_t)rr * (H_ * DV) + c4);
            }
            cpa_commit();
        }
        float* Kd = sm + 128 * QSTR + (t & 1) * 64 * KSTR;
        float* Vd = sm + 128 * QSTR + (2 + (t & 1)) * 64 * KSTR;

        // ---- S = Q K^T : 16 rows x 64 keys per warp ----------------------
        float sc[8][4];
        #pragma unroll
        for (int i = 0; i < 8; ++i)
            #pragma unroll
            for (int e = 0; e < 4; ++e) sc[i][e] = 0.f;
        #pragma unroll
        for (int ks = 0; ks < 16; ++ks) {
            unsigned aq[4];
            const float* qr = Qs + r0l * QSTR + ks * 8 + t4;
            aq[0] = __float_as_uint(qr[0]);
            aq[1] = __float_as_uint(qr[8 * QSTR]);
            aq[2] = __float_as_uint(qr[4]);
            aq[3] = __float_as_uint(qr[8 * QSTR + 4]);
            #pragma unroll
            for (int nf = 0; nf < 8; ++nf) {
                unsigned kb2[2];
                const float* kr = Kd + (nf * 8 + g) * KSTR + ks * 8 + t4;
                kb2[0] = __float_as_uint(kr[0]);
                kb2[1] = __float_as_uint(kr[4]);
                mma8(sc[nf], aq, kb2);
            }
        }
        // ---- causal mask -------------------------------------------------
        if (t >= 2 * qt) {
            #pragma unroll
            for (int nf = 0; nf < 8; ++nf) {
                int k0 = t * 64 + nf * 8 + 2 * t4;
                if (k0     > r0gl)     sc[nf][0] = -1e30f;
                if (k0 + 1 > r0gl)     sc[nf][1] = -1e30f;
                if (k0     > r0gl + 8) sc[nf][2] = -1e30f;
                if (k0 + 1 > r0gl + 8) sc[nf][3] = -1e30f;
            }
        }
        // ---- online softmax on register fragments ------------------------
        float ml0 = -1e30f, ml1 = -1e30f;
        #pragma unroll
        for (int nf = 0; nf < 8; ++nf) {
            ml0 = fmaxf(ml0, fmaxf(sc[nf][0], sc[nf][1]));
            ml1 = fmaxf(ml1, fmaxf(sc[nf][2], sc[nf][3]));
        }
        ml0 = fmaxf(ml0, __shfl_xor_sync(0xffffffffu, ml0, 1));
        ml0 = fmaxf(ml0, __shfl_xor_sync(0xffffffffu, ml0, 2));
        ml1 = fmaxf(ml1, __shfl_xor_sync(0xffffffffu, ml1, 1));
        ml1 = fmaxf(ml1, __shfl_xor_sync(0xffffffffu, ml1, 2));
        float mn0 = fmaxf(m0, ml0), mn1 = fmaxf(m1, ml1);
        float a0 = __expf(m0 - mn0), a1 = __expf(m1 - mn1);
        float s0 = 0.f, s1 = 0.f;
        #pragma unroll
        for (int nf = 0; nf < 8; ++nf) {
            float p00 = __expf(sc[nf][0] - mn0);
            float p01 = __expf(sc[nf][1] - mn0);
            float p10 = __expf(sc[nf][2] - mn1);
            float p11 = __expf(sc[nf][3] - mn1);
            s0 += p00 + p01; s1 += p10 + p11;
            sc[nf][0] = f2tff(p00); sc[nf][1] = f2tff(p01);
            sc[nf][2] = f2tff(p10); sc[nf][3] = f2tff(p11);
        }
        s0 += __shfl_xor_sync(0xffffffffu, s0, 1);
        s0 += __shfl_xor_sync(0xffffffffu, s0, 2);
        s1 += __shfl_xor_sync(0xffffffffu, s1, 1);
        s1 += __shfl_xor_sync(0xffffffffu, s1, 2);
        l0 = l0 * a0 + s0; l1 = l1 * a1 + s1;
        m0 = mn0; m1 = mn1;
        #pragma unroll
        for (int nf = 0; nf < 16; ++nf) {
            oc[nf][0] *= a0; oc[nf][1] *= a0;
            oc[nf][2] *= a1; oc[nf][3] *= a1;
        }
        // ---- O += P V : C-frag -> A-frag via shfl, then mma --------------
        const int srcA = (lane & ~3) | (t4 >> 1);
        const bool odd = (t4 & 1);
        #pragma unroll
        for (int ks = 0; ks < 8; ++ks) {
            float e0A = __shfl_sync(0xffffffffu, sc[ks][0], srcA);
            float e1A = __shfl_sync(0xffffffffu, sc[ks][1], srcA);
            float e2A = __shfl_sync(0xffffffffu, sc[ks][2], srcA);
            float e3A = __shfl_sync(0xffffffffu, sc[ks][3], srcA);
            float e0B = __shfl_sync(0xffffffffu, sc[ks][0], srcA + 2);
            float e1B = __shfl_sync(0xffffffffu, sc[ks][1], srcA + 2);
            float e2B = __shfl_sync(0xffffffffu, sc[ks][2], srcA + 2);
            float e3B = __shfl_sync(0xffffffffu, sc[ks][3], srcA + 2);
            unsigned pa[4];
            pa[0] = __float_as_uint(odd ? e1A : e0A);
            pa[1] = __float_as_uint(odd ? e3A : e2A);
            pa[2] = __float_as_uint(odd ? e1B : e0B);
            pa[3] = __float_as_uint(odd ? e3B : e2B);
            #pragma unroll
            for (int nf = 0; nf < 16; ++nf) {
                unsigned vb2[2];
                const float* vr = Vd + (ks * 8 + t4) * KSTR + nf * 8 + g;
                vb2[0] = __float_as_uint(vr[0]);
                vb2[1] = __float_as_uint(vr[4 * KSTR]);
                mma8(oc[nf], pa, vb2);
            }
        }
    }
    // ---- epilogue -------------------------------------------------------
    float il0 = 1.0f / l0, il1 = 1.0f / l1;
    float* ob = g_o + ((size_t)(b * S_) + r0gl) * (H_ * DV) + h * DV;
    float* ob1 = ob + 8 * (size_t)(H_ * DV);
    #pragma unroll
    for (int nf = 0; nf < 16; ++nf) {
        int col = nf * 8 + 2 * t4;
        *(float2*)(ob  + col) = make_float2(oc[nf][0] * il0, oc[nf][1] * il0);
        *(float2*)(ob1 + col) = make_float2(oc[nf][2] * il1, oc[nf][3] * il1);
    }
}

// ---------------- launcher ---------------------------------------------------
extern "C" void kernel_launch(void* const* d_in, const int* in_sizes, int n_in,
                              void* d_out, int out_size) {
    const float* x         = (const float*)d_in[0];
    const int*   pos       = (const int*)  d_in[1];
    const float* W_dkv     = (const float*)d_in[2];
    const float* b_dkv     = (const float*)d_in[3];
    const float* W_dq      = (const float*)d_in[4];
    const float* b_dq      = (const float*)d_in[5];
    const float* W_uk_nope = (const float*)d_in[6];
    const float* b_uk_nope = (const float*)d_in[7];
    const float* W_uv      = (const float*)d_in[8];
    const float* b_uv      = (const float*)d_in[9];
    const float* W_uq_nope = (const float*)d_in[10];
    const float* b_uq_nope = (const float*)d_in[11];
    const float* W_uq_rope = (const float*)d_in[12];
    const float* b_uq_rope = (const float*)d_in[13];
    const float* W_uk_rope = (const float*)d_in[14];
    const float* b_uk_rope = (const float*)d_in[15];
    const float* W_o       = (const float*)d_in[16];
    const float* b_o       = (const float*)d_in[17];
    float* out = (float*)d_out;

    float *Ckv, *Cq, *qn, *qr, *kn, *kr, *v, *o;
    cudaGetSymbolAddress((void**)&Ckv, g_Ckv);
    cudaGetSymbolAddress((void**)&Cq,  g_Cq);
    cudaGetSymbolAddress((void**)&qn,  g_qnope);
    cudaGetSymbolAddress((void**)&qr,  g_qrope);
    cudaGetSymbolAddress((void**)&kn,  g_knope);
    cudaGetSymbolAddress((void**)&kr,  g_krope);
    cudaGetSymbolAddress((void**)&v,   g_v);
    cudaGetSymbolAddress((void**)&o,   g_o);

    auto launch2 = [&](GemmJob a, GemmJob b) {
        int nmax = a.N > b.N ? a.N : b.N;
        dim3 grid(nmax / 128, MTOK / 128, 2);
        gemm_tf32_dual<<<grid, 256>>>(a, b);
    };
    auto launch1 = [&](GemmJob a) {
        dim3 grid(a.N / 128, MTOK / 128, 1);
        gemm_tf32_dual<<<grid, 256>>>(a, a);
    };

    // #1: dkv + dq (A = x)
    launch2({x, W_dkv, b_dkv, Ckv, DL, DM, 0}, {x, W_dq, b_dq, Cq, DL, DM, 0});
    // #2: uk_rope (A = x)
    launch1({x, W_uk_rope, b_uk_rope, kr, H_*64, DM, 0});
    // #3: uq_nope + uq_rope (A = Cq)
    launch2({Cq, W_uq_nope, b_uq_nope, qn, H_*64, DL, 0},
            {Cq, W_uq_rope, b_uq_rope, qr, H_*64, DL, 0});
    // #4: uk_nope + uv (A = Ckv); v gets tf32-rounded at producer
    launch2({Ckv, W_uk_nope, b_uk_nope, kn, H_*64, DL, 0},
            {Ckv, W_uv, b_uv, v, H_*DV, DL, 1});
    // #5: pack/rope (q scaled + tf32, k tf32)
    int packTotal = MTOK * 384;
    pack_qk<<<(packTotal + 255) / 256, 256>>>(pos);
    // #6: attention (cp.async pipeline)
    cudaFuncSetAttribute(attn_mma, cudaFuncAttributeMaxDynamicSharedMemorySize,
                         ATT_SMEM);
    attn_mma<<<dim3(S_ / 128, B_ * H_), 256, ATT_SMEM>>>();
    // #7: output projection
    launch1({o, W_o, b_o, out, DM, H_*DV, 0});
}